// round 1
// baseline (speedup 1.0000x reference)
#include <cuda_runtime.h>
#include <math.h>

// Problem constants
#define BATCH 4
#define SEQ   4096
#define DIM   512
#define ROWS  (BATCH * SEQ)          // 16384
#define EPSILON_THR 0.1f
#define LN_EPS 1e-5f
#define NORM_EPS 1e-12f

// GEMM tiling
#define BM 128
#define BN 128
#define BK 16

// Scratch (allocation-free: __device__ globals)
__device__ float g_q[(size_t)ROWS * DIM];                    // 33.5 MB
__device__ float g_v[(size_t)ROWS * DIM];                    // 33.5 MB
__device__ float g_attn[(size_t)BATCH * SEQ * SEQ];          // 268 MB

// ---------------------------------------------------------------------------
// C = A * B^T  (A: [M,K] row-major, B: [N,K] row-major), optional threshold
// grid: (N/BN, M/BM, nbatch); per-batch strides in elements
// ---------------------------------------------------------------------------
__global__ __launch_bounds__(256) void gemm_abt_kernel(
    const float* __restrict__ A, const float* __restrict__ B, float* __restrict__ C,
    int M, int N, int K, long sA, long sB, long sC, int thresh)
{
    __shared__ float As[BK][BM + 4];
    __shared__ float Bs[BK][BN + 4];

    const float* Ab = A + (long)blockIdx.z * sA + (long)blockIdx.y * BM * K;
    const float* Bb = B + (long)blockIdx.z * sB + (long)blockIdx.x * BN * K;
    float*       Cb = C + (long)blockIdx.z * sC;

    int tid = threadIdx.x;
    int tx = tid & 15;
    int ty = tid >> 4;

    float acc[8][8];
#pragma unroll
    for (int i = 0; i < 8; i++)
#pragma unroll
        for (int j = 0; j < 8; j++) acc[i][j] = 0.0f;

    for (int k0 = 0; k0 < K; k0 += BK) {
#pragma unroll
        for (int i = 0; i < 8; i++) {
            int idx = tid + i * 256;         // 0..2047
            int m  = idx >> 4;               // 0..127
            int kk = idx & 15;               // 0..15
            As[kk][m] = Ab[(long)m * K + k0 + kk];
            Bs[kk][m] = Bb[(long)m * K + k0 + kk];
        }
        __syncthreads();

#pragma unroll
        for (int kk = 0; kk < BK; kk++) {
            float a[8], b[8];
#pragma unroll
            for (int i = 0; i < 8; i++) a[i] = As[kk][ty * 8 + i];
#pragma unroll
            for (int j = 0; j < 8; j++) b[j] = Bs[kk][tx * 8 + j];
#pragma unroll
            for (int i = 0; i < 8; i++)
#pragma unroll
                for (int j = 0; j < 8; j++) acc[i][j] += a[i] * b[j];
        }
        __syncthreads();
    }

    int row0 = blockIdx.y * BM + ty * 8;
    int col0 = blockIdx.x * BN + tx * 8;
#pragma unroll
    for (int i = 0; i < 8; i++) {
#pragma unroll
        for (int j = 0; j < 8; j++) {
            float val = acc[i][j];
            if (thresh) val = (val > EPSILON_THR) ? val : 0.0f;
            Cb[(long)(row0 + i) * N + col0 + j] = val;
        }
    }
}

// ---------------------------------------------------------------------------
// C = A * B  (A: [M,K] row-major, B: [K,N] row-major)
// grid: (N/BN, M/BM, nbatch)
// ---------------------------------------------------------------------------
__global__ __launch_bounds__(256) void gemm_ab_kernel(
    const float* __restrict__ A, const float* __restrict__ B, float* __restrict__ C,
    int M, int N, int K, long sA, long sB, long sC)
{
    __shared__ float As[BK][BM + 4];
    __shared__ float Bs[BK][BN + 4];

    const float* Ab = A + (long)blockIdx.z * sA + (long)blockIdx.y * BM * K;
    const float* Bb = B + (long)blockIdx.z * sB + (long)blockIdx.x * BN;
    float*       Cb = C + (long)blockIdx.z * sC;

    int tid = threadIdx.x;
    int tx = tid & 15;
    int ty = tid >> 4;

    float acc[8][8];
#pragma unroll
    for (int i = 0; i < 8; i++)
#pragma unroll
        for (int j = 0; j < 8; j++) acc[i][j] = 0.0f;

    for (int k0 = 0; k0 < K; k0 += BK) {
#pragma unroll
        for (int i = 0; i < 8; i++) {
            int idx = tid + i * 256;
            // A tile: [BM x BK]
            int m  = idx >> 4;
            int kk = idx & 15;
            As[kk][m] = Ab[(long)m * K + k0 + kk];
            // B tile: [BK x BN], coalesced in n
            int n   = idx & 127;
            int kk2 = idx >> 7;
            Bs[kk2][n] = Bb[(long)(k0 + kk2) * N + n];
        }
        __syncthreads();

#pragma unroll
        for (int kk = 0; kk < BK; kk++) {
            float a[8], b[8];
#pragma unroll
            for (int i = 0; i < 8; i++) a[i] = As[kk][ty * 8 + i];
#pragma unroll
            for (int j = 0; j < 8; j++) b[j] = Bs[kk][tx * 8 + j];
#pragma unroll
            for (int i = 0; i < 8; i++)
#pragma unroll
                for (int j = 0; j < 8; j++) acc[i][j] += a[i] * b[j];
        }
        __syncthreads();
    }

    int row0 = blockIdx.y * BM + ty * 8;
    int col0 = blockIdx.x * BN + tx * 8;
#pragma unroll
    for (int i = 0; i < 8; i++)
#pragma unroll
        for (int j = 0; j < 8; j++)
            Cb[(long)(row0 + i) * N + col0 + j] = acc[i][j];
}

// ---------------------------------------------------------------------------
// Block reduce (128 threads)
// ---------------------------------------------------------------------------
__device__ __forceinline__ float block_reduce_sum_128(float v)
{
    __shared__ float sh[4];
#pragma unroll
    for (int o = 16; o > 0; o >>= 1) v += __shfl_down_sync(0xffffffffu, v, o);
    int lane = threadIdx.x & 31;
    int w    = threadIdx.x >> 5;
    if (lane == 0) sh[w] = v;
    __syncthreads();
    float total = sh[0] + sh[1] + sh[2] + sh[3];
    __syncthreads();   // protect sh reuse across calls
    return total;
}

// L2-normalize each row of q (ROWS rows of DIM)
__global__ __launch_bounds__(128) void l2norm_kernel(float* __restrict__ q)
{
    float* p = q + (long)blockIdx.x * DIM;
    float s = 0.0f;
#pragma unroll
    for (int i = threadIdx.x; i < DIM; i += 128) {
        float v = p[i];
        s += v * v;
    }
    float total = block_reduce_sum_128(s);
    float inv = 1.0f / fmaxf(sqrtf(total), NORM_EPS);
#pragma unroll
    for (int i = threadIdx.x; i < DIM; i += 128)
        p[i] *= inv;
}

// LayerNorm over last dim (in place on out)
__global__ __launch_bounds__(128) void layernorm_kernel(
    float* __restrict__ out, const float* __restrict__ gamma, const float* __restrict__ beta)
{
    float* p = out + (long)blockIdx.x * DIM;
    float s = 0.0f, s2 = 0.0f;
    float vals[4];
#pragma unroll
    for (int t = 0; t < 4; t++) {
        int i = threadIdx.x + t * 128;
        float v = p[i];
        vals[t] = v;
        s  += v;
        s2 += v * v;
    }
    float mean   = block_reduce_sum_128(s)  * (1.0f / DIM);
    float meansq = block_reduce_sum_128(s2) * (1.0f / DIM);
    float var = meansq - mean * mean;
    float inv = rsqrtf(var + LN_EPS);
#pragma unroll
    for (int t = 0; t < 4; t++) {
        int i = threadIdx.x + t * 128;
        p[i] = (vals[t] - mean) * inv * gamma[i] + beta[i];
    }
}

// ---------------------------------------------------------------------------
// Launch
// ---------------------------------------------------------------------------
extern "C" void kernel_launch(void* const* d_in, const int* in_sizes, int n_in,
                              void* d_out, int out_size)
{
    const float* x     = (const float*)d_in[0];   // [B,N,D]
    const float* W_qk  = (const float*)d_in[1];   // [Dqk,D]
    const float* W_v   = (const float*)d_in[2];   // [Dv,D]
    const float* gamma = (const float*)d_in[3];   // [Dv]
    const float* beta  = (const float*)d_in[4];   // [Dv]
    float* out = (float*)d_out;

    float *qp, *vp, *attnp;
    cudaGetSymbolAddress((void**)&qp,    g_q);
    cudaGetSymbolAddress((void**)&vp,    g_v);
    cudaGetSymbolAddress((void**)&attnp, g_attn);

    // 1) Projections: q = x * Wqk^T, v = x * Wv^T   (M=16384, N=512, K=512)
    {
        dim3 grid(DIM / BN, ROWS / BM, 1);
        gemm_abt_kernel<<<grid, 256>>>(x, W_qk, qp, ROWS, DIM, DIM, 0, 0, 0, 0);
        gemm_abt_kernel<<<grid, 256>>>(x, W_v,  vp, ROWS, DIM, DIM, 0, 0, 0, 0);
    }

    // 2) L2-normalize q rows
    l2norm_kernel<<<ROWS, 128>>>(qp);

    // 3) S = Qn * Qn^T per batch, thresholded  (M=N=4096, K=512, z=4)
    {
        dim3 grid(SEQ / BN, SEQ / BM, BATCH);
        gemm_abt_kernel<<<grid, 256>>>(qp, qp, attnp, SEQ, SEQ, DIM,
                                       (long)SEQ * DIM, (long)SEQ * DIM,
                                       (long)SEQ * SEQ, 1);
    }

    // 4) out = A * V per batch  (M=4096, N=512, K=4096, z=4)
    {
        dim3 grid(DIM / BN, SEQ / BM, BATCH);
        gemm_ab_kernel<<<grid, 256>>>(attnp, vp, out, SEQ, DIM, SEQ,
                                      (long)SEQ * SEQ, (long)SEQ * DIM,
                                      (long)SEQ * DIM);
    }

    // 5) LayerNorm rows of out
    layernorm_kernel<<<ROWS, 128>>>(out, gamma, beta);
}

// round 3
// speedup vs baseline: 1.2301x; 1.2301x over previous
#include <cuda_runtime.h>
#include <cuda_bf16.h>
#include <cstdint>
#include <math.h>

// ---------------------------------------------------------------------------
// Problem constants
// ---------------------------------------------------------------------------
#define BATCH 4
#define SEQ   4096
#define DIM   512
#define ROWS  (BATCH * SEQ)          // 16384
#define EPS_THR 0.1f
#define BAND    4e-4f
#define LN_EPS  1e-5f
#define NORM_EPS 1e-12f

using bf16 = __nv_bfloat16;

// ---------------------------------------------------------------------------
// Scratch (__device__ globals; no runtime allocation)
// ---------------------------------------------------------------------------
__device__ float g_q  [(size_t)ROWS * DIM];
__device__ float g_v  [(size_t)ROWS * DIM];
__device__ bf16  g_qhi[(size_t)ROWS * DIM];
__device__ bf16  g_qlo[(size_t)ROWS * DIM];
__device__ bf16  g_vthi[(size_t)BATCH * DIM * SEQ];   // vT per batch [512,4096]
__device__ bf16  g_vtlo[(size_t)BATCH * DIM * SEQ];
__device__ bf16  g_shi[(size_t)BATCH * SEQ * SEQ];    // masked attn hi
__device__ bf16  g_slo[(size_t)BATCH * SEQ * SEQ];    // masked attn lo

// ---------------------------------------------------------------------------
// PTX helpers (all arch-agnostic: sm_80+)
// ---------------------------------------------------------------------------
__device__ __forceinline__ uint32_t smem_u32(const void* p) {
    uint32_t a;
    asm("{ .reg .u64 t; cvta.to.shared.u64 t, %1; cvt.u32.u64 %0, t; }"
        : "=r"(a) : "l"(p));
    return a;
}

__device__ __forceinline__ void cp16(uint32_t dst, const void* src) {
    asm volatile("cp.async.cg.shared.global [%0], [%1], 16;" :: "r"(dst), "l"(src));
}
#define CP_COMMIT() asm volatile("cp.async.commit_group;" ::: "memory")
#define CP_WAIT(n)  asm volatile("cp.async.wait_group %0;" :: "n"(n) : "memory")

#define LDSM4(r0, r1, r2, r3, addr) \
    asm volatile("ldmatrix.sync.aligned.m8n8.x4.shared.b16 {%0,%1,%2,%3},[%4];" \
                 : "=r"(r0), "=r"(r1), "=r"(r2), "=r"(r3) : "r"(addr))

__device__ __forceinline__ void mma16816(float* c, const uint32_t* a, const uint32_t* b) {
    asm volatile(
        "mma.sync.aligned.m16n8k16.row.col.f32.bf16.bf16.f32 "
        "{%0,%1,%2,%3},{%4,%5,%6,%7},{%8,%9},{%0,%1,%2,%3};"
        : "+f"(c[0]), "+f"(c[1]), "+f"(c[2]), "+f"(c[3])
        : "r"(a[0]), "r"(a[1]), "r"(a[2]), "r"(a[3]), "r"(b[0]), "r"(b[1]));
}

// swizzled byte-column within a 128B row:  col ^ ((row&7)*16)
#define SWZC(c, r) ((uint32_t)(c) ^ ((((uint32_t)(r)) & 7u) << 4))

// ---------------------------------------------------------------------------
// fp32 SIMT projection GEMM: C = A * B^T  (A:[M,K], B:[N,K] row-major)
// ---------------------------------------------------------------------------
#define BM 128
#define BN 128
#define BK 16
__global__ __launch_bounds__(256) void gemm_abt_kernel(
    const float* __restrict__ A, const float* __restrict__ B, float* __restrict__ C,
    int M, int N, int K)
{
    __shared__ float As[BK][BM + 4];
    __shared__ float Bs[BK][BN + 4];

    const float* Ab = A + (long)blockIdx.y * BM * K;
    const float* Bb = B + (long)blockIdx.x * BN * K;

    int tid = threadIdx.x;
    int tx = tid & 15, ty = tid >> 4;

    float acc[8][8];
#pragma unroll
    for (int i = 0; i < 8; i++)
#pragma unroll
        for (int j = 0; j < 8; j++) acc[i][j] = 0.0f;

    for (int k0 = 0; k0 < K; k0 += BK) {
#pragma unroll
        for (int i = 0; i < 8; i++) {
            int idx = tid + i * 256;
            int m = idx >> 4, kk = idx & 15;
            As[kk][m] = Ab[(long)m * K + k0 + kk];
            Bs[kk][m] = Bb[(long)m * K + k0 + kk];
        }
        __syncthreads();
#pragma unroll
        for (int kk = 0; kk < BK; kk++) {
            float a[8], b[8];
#pragma unroll
            for (int i = 0; i < 8; i++) a[i] = As[kk][ty * 8 + i];
#pragma unroll
            for (int j = 0; j < 8; j++) b[j] = Bs[kk][tx * 8 + j];
#pragma unroll
            for (int i = 0; i < 8; i++)
#pragma unroll
                for (int j = 0; j < 8; j++) acc[i][j] += a[i] * b[j];
        }
        __syncthreads();
    }

    int row0 = blockIdx.y * BM + ty * 8;
    int col0 = blockIdx.x * BN + tx * 8;
#pragma unroll
    for (int i = 0; i < 8; i++)
#pragma unroll
        for (int j = 0; j < 8; j++)
            C[(long)(row0 + i) * N + col0 + j] = acc[i][j];
}

// ---------------------------------------------------------------------------
// Block reduce (128 threads)
// ---------------------------------------------------------------------------
__device__ __forceinline__ float block_reduce_sum_128(float v)
{
    __shared__ float sh[4];
#pragma unroll
    for (int o = 16; o > 0; o >>= 1) v += __shfl_down_sync(0xffffffffu, v, o);
    int lane = threadIdx.x & 31, w = threadIdx.x >> 5;
    if (lane == 0) sh[w] = v;
    __syncthreads();
    float total = sh[0] + sh[1] + sh[2] + sh[3];
    __syncthreads();
    return total;
}

// L2-normalize rows of q in place; emit bf16 hi/lo split
__global__ __launch_bounds__(128) void l2norm_split_kernel(
    float* __restrict__ q, bf16* __restrict__ qhi, bf16* __restrict__ qlo)
{
    long base = (long)blockIdx.x * DIM;
    float* p = q + base;
    float s = 0.0f;
#pragma unroll
    for (int i = threadIdx.x; i < DIM; i += 128) { float v = p[i]; s += v * v; }
    float total = block_reduce_sum_128(s);
    float inv = 1.0f / fmaxf(sqrtf(total), NORM_EPS);
#pragma unroll
    for (int i = threadIdx.x; i < DIM; i += 128) {
        float v = p[i] * inv;
        p[i] = v;
        bf16 h = __float2bfloat16_rn(v);
        qhi[base + i] = h;
        qlo[base + i] = __float2bfloat16_rn(v - __bfloat162float(h));
    }
}

// Transpose v per batch into vT [DIM, SEQ], emitting bf16 hi/lo
__global__ __launch_bounds__(256) void transpose_split_kernel(
    const float* __restrict__ v, bf16* __restrict__ vthi, bf16* __restrict__ vtlo)
{
    __shared__ float t[32][33];
    int bz = blockIdx.z;
    int n0 = blockIdx.x * 32;
    int e0 = blockIdx.y * 32;
    int tx = threadIdx.x & 31, ty = threadIdx.x >> 5;

    const float* src = v + ((long)bz * SEQ + n0) * DIM + e0;
#pragma unroll
    for (int i = 0; i < 4; i++) {
        int r = ty + i * 8;
        t[r][tx] = src[(long)r * DIM + tx];
    }
    __syncthreads();

    bf16* dh = vthi + ((long)bz * DIM + e0) * SEQ + n0;
    bf16* dl = vtlo + ((long)bz * DIM + e0) * SEQ + n0;
#pragma unroll
    for (int i = 0; i < 4; i++) {
        int e = ty + i * 8;
        float val = t[tx][e];
        bf16 h = __float2bfloat16_rn(val);
        dh[(long)e * SEQ + tx] = h;
        dl[(long)e * SEQ + tx] = __float2bfloat16_rn(val - __bfloat162float(h));
    }
}

// ---------------------------------------------------------------------------
// mma.sync bf16 split GEMM: D[128x128] fp32 += (Ahi+Alo)(Bhi+Blo)^T
// 3 passes (hi*hi + hi*lo + lo*hi) accumulating into one fp32 fragment.
// Tiles: CTA 128x128, 8 warps arranged 4(M) x 2(N), warp tile 32x64.
// K chunk 64, cp.async double buffer, XOR-swizzled smem, ldmatrix.
// EPI=0: S epilogue (fp32 band rescue + threshold + bf16 hi/lo store)
// EPI=1: AV epilogue (fp32 store)
// ---------------------------------------------------------------------------
#define KC      64
#define PART_B  16384                  // 128 rows x 128 bytes
#define STAGE_B (4 * PART_B)           // Ahi Alo Bhi Blo = 64KB
#define SMEM_DYN (2 * STAGE_B)         // 128KB double buffered

template<int EPI>
__global__ __launch_bounds__(256, 1) void mma_gemm_kernel(
    const bf16* __restrict__ Ahi, const bf16* __restrict__ Alo, long ldA, long sAb,
    const bf16* __restrict__ Bhi, const bf16* __restrict__ Blo, long ldB, long sBb,
    int K,
    const float* __restrict__ qn,
    bf16* __restrict__ Ohi, bf16* __restrict__ Olo,
    float* __restrict__ Ofp, long ldO, long sOb)
{
    extern __shared__ __align__(1024) char sm[];

    int tid = threadIdx.x;
    int wid = tid >> 5, lane = tid & 31;
    int wm = wid & 3, wn = wid >> 2;            // 4 x 2 warp grid
    int bx = blockIdx.x, by = blockIdx.y, bz = blockIdx.z;

    const bf16* At_hi = Ahi + (long)bz * sAb + (long)by * 128 * ldA;
    const bf16* At_lo = Alo + (long)bz * sAb + (long)by * 128 * ldA;
    const bf16* Bt_hi = Bhi + (long)bz * sBb + (long)bx * 128 * ldB;
    const bf16* Bt_lo = Blo + (long)bz * sBb + (long)bx * 128 * ldB;

    uint32_t smb = smem_u32(sm);
    int NC = K / KC;

    // ---- chunk loader (cp.async) ----
    auto issue_chunk = [&](int c) {
        uint32_t st = smb + (uint32_t)(c & 1) * STAGE_B;
        int k0 = c * KC;
        const bf16* srcs[4] = { At_hi, At_lo, Bt_hi, Bt_lo };
        long lds[4] = { ldA, ldA, ldB, ldB };
#pragma unroll
        for (int p = 0; p < 4; p++) {
#pragma unroll
            for (int i = 0; i < 4; i++) {
                int idx = tid + i * 256;       // 0..1023
                int r = idx >> 3;              // 0..127
                int c8 = idx & 7;              // 16B unit
                uint32_t dst = st + (uint32_t)p * PART_B + (uint32_t)r * 128 + SWZC(c8 * 16, r);
                cp16(dst, srcs[p] + (long)r * lds[p] + k0 + c8 * 8);
            }
        }
        CP_COMMIT();
    };

    float acc[2][8][4];
#pragma unroll
    for (int mt = 0; mt < 2; mt++)
#pragma unroll
        for (int nt = 0; nt < 8; nt++)
#pragma unroll
            for (int i = 0; i < 4; i++) acc[mt][nt][i] = 0.0f;

    issue_chunk(0);

    for (int c = 0; c < NC; c++) {
        if (c + 1 < NC) { issue_chunk(c + 1); CP_WAIT(1); }
        else            { CP_WAIT(0); }
        __syncthreads();

        uint32_t base = smb + (uint32_t)(c & 1) * STAGE_B;
        uint32_t pAh = base, pAl = base + PART_B, pBh = base + 2 * PART_B, pBl = base + 3 * PART_B;

#pragma unroll
        for (int ks = 0; ks < 4; ks++) {
            uint32_t ah[2][4], al[2][4];
#pragma unroll
            for (int mt = 0; mt < 2; mt++) {
                int arow = wm * 32 + mt * 16 + (lane & 15);
                uint32_t off = (uint32_t)arow * 128 + SWZC(ks * 32 + (lane >> 4) * 16, arow);
                LDSM4(ah[mt][0], ah[mt][1], ah[mt][2], ah[mt][3], pAh + off);
                LDSM4(al[mt][0], al[mt][1], al[mt][2], al[mt][3], pAl + off);
            }
#pragma unroll
            for (int np = 0; np < 4; np++) {
                int brow = wn * 64 + np * 16 + (lane & 7) + ((lane >> 4) << 3);
                uint32_t off = (uint32_t)brow * 128 +
                               SWZC(ks * 32 + ((lane >> 3) & 1) * 16, brow);
                uint32_t bh[4], bl[4];
                LDSM4(bh[0], bh[1], bh[2], bh[3], pBh + off);
                LDSM4(bl[0], bl[1], bl[2], bl[3], pBl + off);
#pragma unroll
                for (int mt = 0; mt < 2; mt++) {
                    mma16816(acc[mt][np * 2 + 0], ah[mt], bh + 0);
                    mma16816(acc[mt][np * 2 + 0], ah[mt], bl + 0);
                    mma16816(acc[mt][np * 2 + 0], al[mt], bh + 0);
                    mma16816(acc[mt][np * 2 + 1], ah[mt], bh + 2);
                    mma16816(acc[mt][np * 2 + 1], ah[mt], bl + 2);
                    mma16816(acc[mt][np * 2 + 1], al[mt], bh + 2);
                }
            }
        }
        __syncthreads();
    }

    // ---- epilogue ----
    const float* qnB = (EPI == 0) ? (qn + (long)bz * SEQ * DIM) : nullptr;

#pragma unroll
    for (int mt = 0; mt < 2; mt++) {
#pragma unroll
        for (int half = 0; half < 2; half++) {
            int gr = by * 128 + wm * 32 + mt * 16 + (lane >> 2) + half * 8;  // row in batch
            if (EPI == 0) {
                const float* qA = qnB + (long)gr * DIM;
#pragma unroll
                for (int nt = 0; nt < 8; nt++) {
                    float s0 = acc[mt][nt][half * 2 + 0];
                    float s1 = acc[mt][nt][half * 2 + 1];
                    int gn0 = bx * 128 + wn * 64 + nt * 8 + (lane & 3) * 2;
                    if (fabsf(s0 - EPS_THR) < BAND) {
                        const float* qB = qnB + (long)gn0 * DIM;
                        float a2 = 0.f;
#pragma unroll 8
                        for (int k = 0; k < DIM; k++) a2 = fmaf(qA[k], qB[k], a2);
                        s0 = a2;
                    }
                    if (fabsf(s1 - EPS_THR) < BAND) {
                        const float* qB = qnB + (long)(gn0 + 1) * DIM;
                        float a2 = 0.f;
#pragma unroll 8
                        for (int k = 0; k < DIM; k++) a2 = fmaf(qA[k], qB[k], a2);
                        s1 = a2;
                    }
                    s0 = (s0 > EPS_THR) ? s0 : 0.f;
                    s1 = (s1 > EPS_THR) ? s1 : 0.f;
                    __nv_bfloat162 hh, ll;
                    hh.x = __float2bfloat16_rn(s0);
                    hh.y = __float2bfloat16_rn(s1);
                    ll.x = __float2bfloat16_rn(s0 - __bfloat162float(hh.x));
                    ll.y = __float2bfloat16_rn(s1 - __bfloat162float(hh.y));
                    long off = (long)bz * sOb + (long)gr * ldO + gn0;
                    *reinterpret_cast<__nv_bfloat162*>(Ohi + off) = hh;
                    *reinterpret_cast<__nv_bfloat162*>(Olo + off) = ll;
                }
            } else {
#pragma unroll
                for (int nt = 0; nt < 8; nt++) {
                    int gn0 = bx * 128 + wn * 64 + nt * 8 + (lane & 3) * 2;
                    long off = (long)bz * sOb + (long)gr * ldO + gn0;
                    float2 f2;
                    f2.x = acc[mt][nt][half * 2 + 0];
                    f2.y = acc[mt][nt][half * 2 + 1];
                    *reinterpret_cast<float2*>(Ofp + off) = f2;
                }
            }
        }
    }
}

// ---------------------------------------------------------------------------
// LayerNorm rows of out
// ---------------------------------------------------------------------------
__global__ __launch_bounds__(128) void layernorm_kernel(
    float* __restrict__ out, const float* __restrict__ gamma, const float* __restrict__ beta)
{
    float* p = out + (long)blockIdx.x * DIM;
    float s = 0.0f, s2 = 0.0f;
    float vals[4];
#pragma unroll
    for (int t = 0; t < 4; t++) {
        int i = threadIdx.x + t * 128;
        float v = p[i];
        vals[t] = v;
        s += v; s2 += v * v;
    }
    float mean   = block_reduce_sum_128(s)  * (1.0f / DIM);
    float meansq = block_reduce_sum_128(s2) * (1.0f / DIM);
    float var = meansq - mean * mean;
    float inv = rsqrtf(var + LN_EPS);
#pragma unroll
    for (int t = 0; t < 4; t++) {
        int i = threadIdx.x + t * 128;
        p[i] = (vals[t] - mean) * inv * gamma[i] + beta[i];
    }
}

// ---------------------------------------------------------------------------
// Launch
// ---------------------------------------------------------------------------
extern "C" void kernel_launch(void* const* d_in, const int* in_sizes, int n_in,
                              void* d_out, int out_size)
{
    const float* x     = (const float*)d_in[0];
    const float* W_qk  = (const float*)d_in[1];
    const float* W_v   = (const float*)d_in[2];
    const float* gamma = (const float*)d_in[3];
    const float* beta  = (const float*)d_in[4];
    float* out = (float*)d_out;

    float *qp, *vp;
    bf16 *qhi, *qlo, *vthi, *vtlo, *shi, *slo;
    cudaGetSymbolAddress((void**)&qp,   g_q);
    cudaGetSymbolAddress((void**)&vp,   g_v);
    cudaGetSymbolAddress((void**)&qhi,  g_qhi);
    cudaGetSymbolAddress((void**)&qlo,  g_qlo);
    cudaGetSymbolAddress((void**)&vthi, g_vthi);
    cudaGetSymbolAddress((void**)&vtlo, g_vtlo);
    cudaGetSymbolAddress((void**)&shi,  g_shi);
    cudaGetSymbolAddress((void**)&slo,  g_slo);

    cudaFuncSetAttribute(mma_gemm_kernel<0>, cudaFuncAttributeMaxDynamicSharedMemorySize, SMEM_DYN);
    cudaFuncSetAttribute(mma_gemm_kernel<1>, cudaFuncAttributeMaxDynamicSharedMemorySize, SMEM_DYN);

    // 1) fp32 projections (q path must be fp32-exact for the threshold)
    {
        dim3 grid(DIM / BN, ROWS / BM, 1);
        gemm_abt_kernel<<<grid, 256>>>(x, W_qk, qp, ROWS, DIM, DIM);
        gemm_abt_kernel<<<grid, 256>>>(x, W_v,  vp, ROWS, DIM, DIM);
    }

    // 2) L2-normalize q rows + bf16 split
    l2norm_split_kernel<<<ROWS, 128>>>(qp, qhi, qlo);

    // 3) Transpose + split v -> vT hi/lo
    {
        dim3 grid(SEQ / 32, DIM / 32, BATCH);
        transpose_split_kernel<<<grid, 256>>>(vp, vthi, vtlo);
    }

    // 4) S = Qn*Qn^T (3-pass bf16 split + fp32 band rescue + threshold), hi/lo store
    {
        dim3 grid(SEQ / 128, SEQ / 128, BATCH);
        mma_gemm_kernel<0><<<grid, 256, SMEM_DYN>>>(
            qhi, qlo, DIM, (long)SEQ * DIM,
            qhi, qlo, DIM, (long)SEQ * DIM,
            DIM, qp,
            shi, slo, nullptr, SEQ, (long)SEQ * SEQ);
    }

    // 5) out = S * V (3-pass bf16 split), fp32 store
    {
        dim3 grid(DIM / 128, SEQ / 128, BATCH);
        mma_gemm_kernel<1><<<grid, 256, SMEM_DYN>>>(
            shi, slo, SEQ, (long)SEQ * SEQ,
            vthi, vtlo, SEQ, (long)DIM * SEQ,
            SEQ, nullptr,
            nullptr, nullptr, out, DIM, (long)SEQ * DIM);
    }

    // 6) LayerNorm
    layernorm_kernel<<<ROWS, 128>>>(out, gamma, beta);
}

// round 4
// speedup vs baseline: 1.7359x; 1.4111x over previous
#include <cuda_runtime.h>
#include <cuda_bf16.h>
#include <cstdint>
#include <math.h>

// ---------------------------------------------------------------------------
// Problem constants
// ---------------------------------------------------------------------------
#define BATCH 4
#define SEQ   4096
#define DIM   512
#define ROWS  (BATCH * SEQ)          // 16384
#define EPS_THR 0.1f
#define BAND    4e-4f
#define LN_EPS  1e-5f
#define NORM_EPS 1e-12f

using bf16 = __nv_bfloat16;

// ---------------------------------------------------------------------------
// Scratch (__device__ globals; no runtime allocation)
// ---------------------------------------------------------------------------
__device__ float g_q  [(size_t)ROWS * DIM];
__device__ float g_v  [(size_t)ROWS * DIM];
__device__ bf16  g_qhi[(size_t)ROWS * DIM];
__device__ bf16  g_qlo[(size_t)ROWS * DIM];
__device__ bf16  g_vthi[(size_t)BATCH * DIM * SEQ];   // vT per batch [512,4096]
__device__ bf16  g_vtlo[(size_t)BATCH * DIM * SEQ];
__device__ bf16  g_shi[(size_t)BATCH * SEQ * SEQ];    // masked attn hi
__device__ bf16  g_slo[(size_t)BATCH * SEQ * SEQ];    // masked attn lo

// ---------------------------------------------------------------------------
// PTX helpers (arch-agnostic: sm_80+)
// ---------------------------------------------------------------------------
__device__ __forceinline__ uint32_t smem_u32(const void* p) {
    uint32_t a;
    asm("{ .reg .u64 t; cvta.to.shared.u64 t, %1; cvt.u32.u64 %0, t; }"
        : "=r"(a) : "l"(p));
    return a;
}

__device__ __forceinline__ void cp16(uint32_t dst, const void* src) {
    asm volatile("cp.async.cg.shared.global [%0], [%1], 16;" :: "r"(dst), "l"(src));
}
#define CP_COMMIT() asm volatile("cp.async.commit_group;" ::: "memory")
#define CP_WAIT(n)  asm volatile("cp.async.wait_group %0;" :: "n"(n) : "memory")

#define LDSM4(r0, r1, r2, r3, addr) \
    asm volatile("ldmatrix.sync.aligned.m8n8.x4.shared.b16 {%0,%1,%2,%3},[%4];" \
                 : "=r"(r0), "=r"(r1), "=r"(r2), "=r"(r3) : "r"(addr))

__device__ __forceinline__ void mma16816(float* c, const uint32_t* a, const uint32_t* b) {
    asm volatile(
        "mma.sync.aligned.m16n8k16.row.col.f32.bf16.bf16.f32 "
        "{%0,%1,%2,%3},{%4,%5,%6,%7},{%8,%9},{%0,%1,%2,%3};"
        : "+f"(c[0]), "+f"(c[1]), "+f"(c[2]), "+f"(c[3])
        : "r"(a[0]), "r"(a[1]), "r"(a[2]), "r"(a[3]), "r"(b[0]), "r"(b[1]));
}

// swizzled byte-column within a 128B row:  col ^ ((row&7)*16)
#define SWZC(c, r) ((uint32_t)(c) ^ ((((uint32_t)(r)) & 7u) << 4))

// ---------------------------------------------------------------------------
// fp32 SIMT projection GEMM: C = A * B^T
// ---------------------------------------------------------------------------
#define BM 128
#define BN 128
#define BK 16
__global__ __launch_bounds__(256) void gemm_abt_kernel(
    const float* __restrict__ A, const float* __restrict__ B, float* __restrict__ C,
    int M, int N, int K)
{
    __shared__ float As[BK][BM + 4];
    __shared__ float Bs[BK][BN + 4];

    const float* Ab = A + (long)blockIdx.y * BM * K;
    const float* Bb = B + (long)blockIdx.x * BN * K;

    int tid = threadIdx.x;
    int tx = tid & 15, ty = tid >> 4;

    float acc[8][8];
#pragma unroll
    for (int i = 0; i < 8; i++)
#pragma unroll
        for (int j = 0; j < 8; j++) acc[i][j] = 0.0f;

    for (int k0 = 0; k0 < K; k0 += BK) {
#pragma unroll
        for (int i = 0; i < 8; i++) {
            int idx = tid + i * 256;
            int m = idx >> 4, kk = idx & 15;
            As[kk][m] = Ab[(long)m * K + k0 + kk];
            Bs[kk][m] = Bb[(long)m * K + k0 + kk];
        }
        __syncthreads();
#pragma unroll
        for (int kk = 0; kk < BK; kk++) {
            float a[8], b[8];
#pragma unroll
            for (int i = 0; i < 8; i++) a[i] = As[kk][ty * 8 + i];
#pragma unroll
            for (int j = 0; j < 8; j++) b[j] = Bs[kk][tx * 8 + j];
#pragma unroll
            for (int i = 0; i < 8; i++)
#pragma unroll
                for (int j = 0; j < 8; j++) acc[i][j] += a[i] * b[j];
        }
        __syncthreads();
    }

    int row0 = blockIdx.y * BM + ty * 8;
    int col0 = blockIdx.x * BN + tx * 8;
#pragma unroll
    for (int i = 0; i < 8; i++)
#pragma unroll
        for (int j = 0; j < 8; j++)
            C[(long)(row0 + i) * N + col0 + j] = acc[i][j];
}

// ---------------------------------------------------------------------------
// Block reduce (128 threads)
// ---------------------------------------------------------------------------
__device__ __forceinline__ float block_reduce_sum_128(float v)
{
    __shared__ float sh[4];
#pragma unroll
    for (int o = 16; o > 0; o >>= 1) v += __shfl_down_sync(0xffffffffu, v, o);
    int lane = threadIdx.x & 31, w = threadIdx.x >> 5;
    if (lane == 0) sh[w] = v;
    __syncthreads();
    float total = sh[0] + sh[1] + sh[2] + sh[3];
    __syncthreads();
    return total;
}

__global__ __launch_bounds__(128) void l2norm_split_kernel(
    float* __restrict__ q, bf16* __restrict__ qhi, bf16* __restrict__ qlo)
{
    long base = (long)blockIdx.x * DIM;
    float* p = q + base;
    float s = 0.0f;
#pragma unroll
    for (int i = threadIdx.x; i < DIM; i += 128) { float v = p[i]; s += v * v; }
    float total = block_reduce_sum_128(s);
    float inv = 1.0f / fmaxf(sqrtf(total), NORM_EPS);
#pragma unroll
    for (int i = threadIdx.x; i < DIM; i += 128) {
        float v = p[i] * inv;
        p[i] = v;
        bf16 h = __float2bfloat16_rn(v);
        qhi[base + i] = h;
        qlo[base + i] = __float2bfloat16_rn(v - __bfloat162float(h));
    }
}

__global__ __launch_bounds__(256) void transpose_split_kernel(
    const float* __restrict__ v, bf16* __restrict__ vthi, bf16* __restrict__ vtlo)
{
    __shared__ float t[32][33];
    int bz = blockIdx.z;
    int n0 = blockIdx.x * 32;
    int e0 = blockIdx.y * 32;
    int tx = threadIdx.x & 31, ty = threadIdx.x >> 5;

    const float* src = v + ((long)bz * SEQ + n0) * DIM + e0;
#pragma unroll
    for (int i = 0; i < 4; i++) {
        int r = ty + i * 8;
        t[r][tx] = src[(long)r * DIM + tx];
    }
    __syncthreads();

    bf16* dh = vthi + ((long)bz * DIM + e0) * SEQ + n0;
    bf16* dl = vtlo + ((long)bz * DIM + e0) * SEQ + n0;
#pragma unroll
    for (int i = 0; i < 4; i++) {
        int e = ty + i * 8;
        float val = t[tx][e];
        bf16 h = __float2bfloat16_rn(val);
        dh[(long)e * SEQ + tx] = h;
        dl[(long)e * SEQ + tx] = __float2bfloat16_rn(val - __bfloat162float(h));
    }
}

// ---------------------------------------------------------------------------
// mma.sync bf16 split GEMM. Pass-major MMA order (no dependent chains).
// EPI=0: S epilogue (triangular grid, band rescue, threshold, bf16 hi/lo store
//        + symmetric mirror write via smem-staged transpose)
// EPI=1: AV epilogue (fp32 store)
// ---------------------------------------------------------------------------
#define KC      64
#define PART_B  16384                  // 128 rows x 128 bytes
#define STAGE_B (4 * PART_B)           // 64KB
#define SMEM_DYN (2 * STAGE_B)         // 128KB

#define TSTRIDE 136                    // bf16 elements per staged row

template<int EPI>
__global__ __launch_bounds__(256, 1) void mma_gemm_kernel(
    const bf16* __restrict__ Ahi, const bf16* __restrict__ Alo, long ldA, long sAb,
    const bf16* __restrict__ Bhi, const bf16* __restrict__ Blo, long ldB, long sBb,
    int K,
    const float* __restrict__ qn,
    bf16* __restrict__ Ohi, bf16* __restrict__ Olo,
    float* __restrict__ Ofp, long ldO, long sOb)
{
    extern __shared__ __align__(1024) char sm[];

    int tid = threadIdx.x;
    int wid = tid >> 5, lane = tid & 31;
    int wm = wid & 3, wn = wid >> 2;            // 4 x 2 warp grid
    int bz = blockIdx.z;

    int bx, by;
    if (EPI == 0) {
        // triangular enumeration: t -> (by=j, bx=i), j<=i
        int t = blockIdx.x;
        int i = (int)((sqrtf(8.0f * (float)t + 1.0f) - 1.0f) * 0.5f);
        while ((i + 1) * (i + 2) / 2 <= t) ++i;
        while (i * (i + 1) / 2 > t) --i;
        by = t - i * (i + 1) / 2;
        bx = i;
    } else {
        bx = blockIdx.x;
        by = blockIdx.y;
    }

    const bf16* At_hi = Ahi + (long)bz * sAb + (long)by * 128 * ldA;
    const bf16* At_lo = Alo + (long)bz * sAb + (long)by * 128 * ldA;
    const bf16* Bt_hi = Bhi + (long)bz * sBb + (long)bx * 128 * ldB;
    const bf16* Bt_lo = Blo + (long)bz * sBb + (long)bx * 128 * ldB;

    uint32_t smb = smem_u32(sm);
    int NC = K / KC;

    auto issue_chunk = [&](int c) {
        uint32_t st = smb + (uint32_t)(c & 1) * STAGE_B;
        int k0 = c * KC;
        const bf16* srcs[4] = { At_hi, At_lo, Bt_hi, Bt_lo };
        long lds[4] = { ldA, ldA, ldB, ldB };
#pragma unroll
        for (int p = 0; p < 4; p++) {
#pragma unroll
            for (int i = 0; i < 4; i++) {
                int idx = tid + i * 256;
                int r = idx >> 3;
                int c8 = idx & 7;
                uint32_t dst = st + (uint32_t)p * PART_B + (uint32_t)r * 128 + SWZC(c8 * 16, r);
                cp16(dst, srcs[p] + (long)r * lds[p] + k0 + c8 * 8);
            }
        }
        CP_COMMIT();
    };

    float acc[2][8][4];
#pragma unroll
    for (int mt = 0; mt < 2; mt++)
#pragma unroll
        for (int nt = 0; nt < 8; nt++)
#pragma unroll
            for (int i = 0; i < 4; i++) acc[mt][nt][i] = 0.0f;

    issue_chunk(0);

    for (int c = 0; c < NC; c++) {
        if (c + 1 < NC) { issue_chunk(c + 1); CP_WAIT(1); }
        else            { CP_WAIT(0); }
        __syncthreads();

        uint32_t base = smb + (uint32_t)(c & 1) * STAGE_B;
        uint32_t pAh = base, pAl = base + PART_B, pBh = base + 2 * PART_B, pBl = base + 3 * PART_B;

#pragma unroll
        for (int ks = 0; ks < 4; ks++) {
            uint32_t ah[2][4], al[2][4], bh[4][4], bl[4][4];
#pragma unroll
            for (int mt = 0; mt < 2; mt++) {
                int arow = wm * 32 + mt * 16 + (lane & 15);
                uint32_t off = (uint32_t)arow * 128 + SWZC(ks * 32 + (lane >> 4) * 16, arow);
                LDSM4(ah[mt][0], ah[mt][1], ah[mt][2], ah[mt][3], pAh + off);
                LDSM4(al[mt][0], al[mt][1], al[mt][2], al[mt][3], pAl + off);
            }
#pragma unroll
            for (int np = 0; np < 4; np++) {
                int brow = wn * 64 + np * 16 + (lane & 7) + ((lane >> 4) << 3);
                uint32_t off = (uint32_t)brow * 128 +
                               SWZC(ks * 32 + ((lane >> 3) & 1) * 16, brow);
                LDSM4(bh[np][0], bh[np][1], bh[np][2], bh[np][3], pBh + off);
                LDSM4(bl[np][0], bl[np][1], bl[np][2], bl[np][3], pBl + off);
            }
            // pass 1: hi*hi — 16 independent accumulators
#pragma unroll
            for (int np = 0; np < 4; np++)
#pragma unroll
                for (int mt = 0; mt < 2; mt++) {
                    mma16816(acc[mt][np * 2 + 0], ah[mt], bh[np] + 0);
                    mma16816(acc[mt][np * 2 + 1], ah[mt], bh[np] + 2);
                }
            // pass 2: hi*lo
#pragma unroll
            for (int np = 0; np < 4; np++)
#pragma unroll
                for (int mt = 0; mt < 2; mt++) {
                    mma16816(acc[mt][np * 2 + 0], ah[mt], bl[np] + 0);
                    mma16816(acc[mt][np * 2 + 1], ah[mt], bl[np] + 2);
                }
            // pass 3: lo*hi
#pragma unroll
            for (int np = 0; np < 4; np++)
#pragma unroll
                for (int mt = 0; mt < 2; mt++) {
                    mma16816(acc[mt][np * 2 + 0], al[mt], bh[np] + 0);
                    mma16816(acc[mt][np * 2 + 1], al[mt], bh[np] + 2);
                }
        }
        __syncthreads();
    }

    // ---- epilogue ----
    const float* qnB = (EPI == 0) ? (qn + (long)bz * SEQ * DIM) : nullptr;
    bf16* smTh = reinterpret_cast<bf16*>(sm);
    bf16* smTl = smTh + 128 * TSTRIDE;
    bool mirror = (EPI == 0) && (bx != by);

#pragma unroll
    for (int mt = 0; mt < 2; mt++) {
#pragma unroll
        for (int half = 0; half < 2; half++) {
            int gr = by * 128 + wm * 32 + mt * 16 + (lane >> 2) + half * 8;
            int lr = wm * 32 + mt * 16 + (lane >> 2) + half * 8;     // local row
            if (EPI == 0) {
                const float* qA = qnB + (long)gr * DIM;
#pragma unroll
                for (int nt = 0; nt < 8; nt++) {
                    float s0 = acc[mt][nt][half * 2 + 0];
                    float s1 = acc[mt][nt][half * 2 + 1];
                    int ln0 = wn * 64 + nt * 8 + (lane & 3) * 2;     // local col
                    int gn0 = bx * 128 + ln0;
                    if (fabsf(s0 - EPS_THR) < BAND) {
                        const float* qB = qnB + (long)gn0 * DIM;
                        float a2 = 0.f;
#pragma unroll 8
                        for (int k = 0; k < DIM; k++) a2 = fmaf(qA[k], qB[k], a2);
                        s0 = a2;
                    }
                    if (fabsf(s1 - EPS_THR) < BAND) {
                        const float* qB = qnB + (long)(gn0 + 1) * DIM;
                        float a2 = 0.f;
#pragma unroll 8
                        for (int k = 0; k < DIM; k++) a2 = fmaf(qA[k], qB[k], a2);
                        s1 = a2;
                    }
                    s0 = (s0 > EPS_THR) ? s0 : 0.f;
                    s1 = (s1 > EPS_THR) ? s1 : 0.f;
                    __nv_bfloat162 hh, ll;
                    hh.x = __float2bfloat16_rn(s0);
                    hh.y = __float2bfloat16_rn(s1);
                    ll.x = __float2bfloat16_rn(s0 - __bfloat162float(hh.x));
                    ll.y = __float2bfloat16_rn(s1 - __bfloat162float(hh.y));
                    long off = (long)bz * sOb + (long)gr * ldO + gn0;
                    *reinterpret_cast<__nv_bfloat162*>(Ohi + off) = hh;
                    *reinterpret_cast<__nv_bfloat162*>(Olo + off) = ll;
                    if (mirror) {
                        smTh[ln0 * TSTRIDE + lr]       = hh.x;
                        smTh[(ln0 + 1) * TSTRIDE + lr] = hh.y;
                        smTl[ln0 * TSTRIDE + lr]       = ll.x;
                        smTl[(ln0 + 1) * TSTRIDE + lr] = ll.y;
                    }
                }
            } else {
#pragma unroll
                for (int nt = 0; nt < 8; nt++) {
                    int gn0 = bx * 128 + wn * 64 + nt * 8 + (lane & 3) * 2;
                    long off = (long)bz * sOb + (long)gr * ldO + gn0;
                    float2 f2;
                    f2.x = acc[mt][nt][half * 2 + 0];
                    f2.y = acc[mt][nt][half * 2 + 1];
                    *reinterpret_cast<float2*>(Ofp + off) = f2;
                }
            }
        }
    }

    if (mirror) {
        __syncthreads();
        int r2 = tid >> 1, half = tid & 1;
        const uint4* srh = reinterpret_cast<const uint4*>(smTh + r2 * TSTRIDE + half * 64);
        const uint4* srl = reinterpret_cast<const uint4*>(smTl + r2 * TSTRIDE + half * 64);
        long rowoff = (long)bz * sOb + (long)(bx * 128 + r2) * ldO + by * 128 + half * 64;
        uint4* dh = reinterpret_cast<uint4*>(Ohi + rowoff);
        uint4* dl = reinterpret_cast<uint4*>(Olo + rowoff);
#pragma unroll
        for (int g = 0; g < 8; g++) { dh[g] = srh[g]; dl[g] = srl[g]; }
    }
}

// ---------------------------------------------------------------------------
// LayerNorm rows of out
// ---------------------------------------------------------------------------
__global__ __launch_bounds__(128) void layernorm_kernel(
    float* __restrict__ out, const float* __restrict__ gamma, const float* __restrict__ beta)
{
    float* p = out + (long)blockIdx.x * DIM;
    float s = 0.0f, s2 = 0.0f;
    float vals[4];
#pragma unroll
    for (int t = 0; t < 4; t++) {
        int i = threadIdx.x + t * 128;
        float v = p[i];
        vals[t] = v;
        s += v; s2 += v * v;
    }
    float mean   = block_reduce_sum_128(s)  * (1.0f / DIM);
    float meansq = block_reduce_sum_128(s2) * (1.0f / DIM);
    float var = meansq - mean * mean;
    float inv = rsqrtf(var + LN_EPS);
#pragma unroll
    for (int t = 0; t < 4; t++) {
        int i = threadIdx.x + t * 128;
        p[i] = (vals[t] - mean) * inv * gamma[i] + beta[i];
    }
}

// ---------------------------------------------------------------------------
// Launch
// ---------------------------------------------------------------------------
extern "C" void kernel_launch(void* const* d_in, const int* in_sizes, int n_in,
                              void* d_out, int out_size)
{
    const float* x     = (const float*)d_in[0];
    const float* W_qk  = (const float*)d_in[1];
    const float* W_v   = (const float*)d_in[2];
    const float* gamma = (const float*)d_in[3];
    const float* beta  = (const float*)d_in[4];
    float* out = (float*)d_out;

    float *qp, *vp;
    bf16 *qhi, *qlo, *vthi, *vtlo, *shi, *slo;
    cudaGetSymbolAddress((void**)&qp,   g_q);
    cudaGetSymbolAddress((void**)&vp,   g_v);
    cudaGetSymbolAddress((void**)&qhi,  g_qhi);
    cudaGetSymbolAddress((void**)&qlo,  g_qlo);
    cudaGetSymbolAddress((void**)&vthi, g_vthi);
    cudaGetSymbolAddress((void**)&vtlo, g_vtlo);
    cudaGetSymbolAddress((void**)&shi,  g_shi);
    cudaGetSymbolAddress((void**)&slo,  g_slo);

    cudaFuncSetAttribute(mma_gemm_kernel<0>, cudaFuncAttributeMaxDynamicSharedMemorySize, SMEM_DYN);
    cudaFuncSetAttribute(mma_gemm_kernel<1>, cudaFuncAttributeMaxDynamicSharedMemorySize, SMEM_DYN);

    // 1) fp32 projections
    {
        dim3 grid(DIM / BN, ROWS / BM, 1);
        gemm_abt_kernel<<<grid, 256>>>(x, W_qk, qp, ROWS, DIM, DIM);
        gemm_abt_kernel<<<grid, 256>>>(x, W_v,  vp, ROWS, DIM, DIM);
    }

    // 2) L2-normalize q rows + bf16 split
    l2norm_split_kernel<<<ROWS, 128>>>(qp, qhi, qlo);

    // 3) Transpose + split v -> vT hi/lo
    {
        dim3 grid(SEQ / 32, DIM / 32, BATCH);
        transpose_split_kernel<<<grid, 256>>>(vp, vthi, vtlo);
    }

    // 4) S = Qn*Qn^T — triangular grid (528 of 1024 tiles/batch) + mirror
    {
        dim3 grid((SEQ / 128) * (SEQ / 128 + 1) / 2, 1, BATCH);
        mma_gemm_kernel<0><<<grid, 256, SMEM_DYN>>>(
            qhi, qlo, DIM, (long)SEQ * DIM,
            qhi, qlo, DIM, (long)SEQ * DIM,
            DIM, qp,
            shi, slo, nullptr, SEQ, (long)SEQ * SEQ);
    }

    // 5) out = S * V
    {
        dim3 grid(DIM / 128, SEQ / 128, BATCH);
        mma_gemm_kernel<1><<<grid, 256, SMEM_DYN>>>(
            shi, slo, SEQ, (long)SEQ * SEQ,
            vthi, vtlo, SEQ, (long)DIM * SEQ,
            SEQ, nullptr,
            nullptr, nullptr, out, DIM, (long)SEQ * DIM);
    }

    // 6) LayerNorm
    layernorm_kernel<<<ROWS, 128>>>(out, gamma, beta);
}

// round 5
// speedup vs baseline: 2.2762x; 1.3112x over previous
#include <cuda_runtime.h>
#include <cuda_bf16.h>
#include <cuda_fp16.h>
#include <cstdint>
#include <math.h>

// ---------------------------------------------------------------------------
// Problem constants
// ---------------------------------------------------------------------------
#define BATCH 4
#define SEQ   4096
#define DIM   512
#define ROWS  (BATCH * SEQ)          // 16384
#define EPS_THR 0.1f
#define BAND    4e-4f
#define LN_EPS  1e-5f
#define NORM_EPS 1e-12f

using bf16 = __nv_bfloat16;

// ---------------------------------------------------------------------------
// Scratch (__device__ globals; no runtime allocation)
// ---------------------------------------------------------------------------
__device__ float g_q  [(size_t)ROWS * DIM];           // fp32 q / qn
__device__ half  g_x16[(size_t)ROWS * DIM];           // x in fp16
__device__ half  g_w16[(size_t)DIM * DIM];            // W_v in fp16
__device__ bf16  g_qhi[(size_t)ROWS * DIM];
__device__ bf16  g_qlo[(size_t)ROWS * DIM];
__device__ half  g_vt16[(size_t)BATCH * DIM * SEQ];   // vT per batch [512,4096]
__device__ half  g_s16[(size_t)BATCH * SEQ * SEQ];    // masked attn, fp16

// ---------------------------------------------------------------------------
// PTX helpers (arch-agnostic: sm_80+)
// ---------------------------------------------------------------------------
__device__ __forceinline__ uint32_t smem_u32(const void* p) {
    uint32_t a;
    asm("{ .reg .u64 t; cvta.to.shared.u64 t, %1; cvt.u32.u64 %0, t; }"
        : "=r"(a) : "l"(p));
    return a;
}

__device__ __forceinline__ void cp16(uint32_t dst, const void* src) {
    asm volatile("cp.async.cg.shared.global [%0], [%1], 16;" :: "r"(dst), "l"(src));
}
#define CP_COMMIT() asm volatile("cp.async.commit_group;" ::: "memory")
#define CP_WAIT(n)  asm volatile("cp.async.wait_group %0;" :: "n"(n) : "memory")

#define LDSM4(r0, r1, r2, r3, addr) \
    asm volatile("ldmatrix.sync.aligned.m8n8.x4.shared.b16 {%0,%1,%2,%3},[%4];" \
                 : "=r"(r0), "=r"(r1), "=r"(r2), "=r"(r3) : "r"(addr))

__device__ __forceinline__ void mma_bf(float* c, const uint32_t* a, const uint32_t* b) {
    asm volatile(
        "mma.sync.aligned.m16n8k16.row.col.f32.bf16.bf16.f32 "
        "{%0,%1,%2,%3},{%4,%5,%6,%7},{%8,%9},{%0,%1,%2,%3};"
        : "+f"(c[0]), "+f"(c[1]), "+f"(c[2]), "+f"(c[3])
        : "r"(a[0]), "r"(a[1]), "r"(a[2]), "r"(a[3]), "r"(b[0]), "r"(b[1]));
}
__device__ __forceinline__ void mma_fp(float* c, const uint32_t* a, const uint32_t* b) {
    asm volatile(
        "mma.sync.aligned.m16n8k16.row.col.f32.f16.f16.f32 "
        "{%0,%1,%2,%3},{%4,%5,%6,%7},{%8,%9},{%0,%1,%2,%3};"
        : "+f"(c[0]), "+f"(c[1]), "+f"(c[2]), "+f"(c[3])
        : "r"(a[0]), "r"(a[1]), "r"(a[2]), "r"(a[3]), "r"(b[0]), "r"(b[1]));
}

// swizzled byte-column within a 128B row
#define SWZC(c, r) ((uint32_t)(c) ^ ((((uint32_t)(r)) & 7u) << 4))

// ---------------------------------------------------------------------------
// fp32 SIMT projection GEMM (q only): C = A * B^T
// ---------------------------------------------------------------------------
#define BM 128
#define BN 128
#define BK 16
__global__ __launch_bounds__(256) void gemm_abt_kernel(
    const float* __restrict__ A, const float* __restrict__ B, float* __restrict__ C,
    int M, int N, int K)
{
    __shared__ float As[BK][BM + 4];
    __shared__ float Bs[BK][BN + 4];

    const float* Ab = A + (long)blockIdx.y * BM * K;
    const float* Bb = B + (long)blockIdx.x * BN * K;

    int tid = threadIdx.x;
    int tx = tid & 15, ty = tid >> 4;

    float acc[8][8];
#pragma unroll
    for (int i = 0; i < 8; i++)
#pragma unroll
        for (int j = 0; j < 8; j++) acc[i][j] = 0.0f;

    for (int k0 = 0; k0 < K; k0 += BK) {
#pragma unroll
        for (int i = 0; i < 8; i++) {
            int idx = tid + i * 256;
            int m = idx >> 4, kk = idx & 15;
            As[kk][m] = Ab[(long)m * K + k0 + kk];
            Bs[kk][m] = Bb[(long)m * K + k0 + kk];
        }
        __syncthreads();
#pragma unroll
        for (int kk = 0; kk < BK; kk++) {
            float a[8], b[8];
#pragma unroll
            for (int i = 0; i < 8; i++) a[i] = As[kk][ty * 8 + i];
#pragma unroll
            for (int j = 0; j < 8; j++) b[j] = Bs[kk][tx * 8 + j];
#pragma unroll
            for (int i = 0; i < 8; i++)
#pragma unroll
                for (int j = 0; j < 8; j++) acc[i][j] += a[i] * b[j];
        }
        __syncthreads();
    }

    int row0 = blockIdx.y * BM + ty * 8;
    int col0 = blockIdx.x * BN + tx * 8;
#pragma unroll
    for (int i = 0; i < 8; i++)
#pragma unroll
        for (int j = 0; j < 8; j++)
            C[(long)(row0 + i) * N + col0 + j] = acc[i][j];
}

// ---------------------------------------------------------------------------
// fp32 -> fp16 convert (n multiple of 4)
// ---------------------------------------------------------------------------
__global__ __launch_bounds__(256) void f2h_kernel(
    const float* __restrict__ src, half* __restrict__ dst, long n)
{
    long i = ((long)blockIdx.x * 256 + threadIdx.x) * 4;
    if (i < n) {
        float4 f = *reinterpret_cast<const float4*>(src + i);
        half2 h0 = __floats2half2_rn(f.x, f.y);
        half2 h1 = __floats2half2_rn(f.z, f.w);
        uint2 u;
        u.x = *reinterpret_cast<uint32_t*>(&h0);
        u.y = *reinterpret_cast<uint32_t*>(&h1);
        *reinterpret_cast<uint2*>(dst + i) = u;
    }
}

// ---------------------------------------------------------------------------
// Block reduce (128 threads)
// ---------------------------------------------------------------------------
__device__ __forceinline__ float block_reduce_sum_128(float v)
{
    __shared__ float sh[4];
#pragma unroll
    for (int o = 16; o > 0; o >>= 1) v += __shfl_down_sync(0xffffffffu, v, o);
    int lane = threadIdx.x & 31, w = threadIdx.x >> 5;
    if (lane == 0) sh[w] = v;
    __syncthreads();
    float total = sh[0] + sh[1] + sh[2] + sh[3];
    __syncthreads();
    return total;
}

__global__ __launch_bounds__(128) void l2norm_split_kernel(
    float* __restrict__ q, bf16* __restrict__ qhi, bf16* __restrict__ qlo)
{
    long base = (long)blockIdx.x * DIM;
    float* p = q + base;
    float s = 0.0f;
#pragma unroll
    for (int i = threadIdx.x; i < DIM; i += 128) { float v = p[i]; s += v * v; }
    float total = block_reduce_sum_128(s);
    float inv = 1.0f / fmaxf(sqrtf(total), NORM_EPS);
#pragma unroll
    for (int i = threadIdx.x; i < DIM; i += 128) {
        float v = p[i] * inv;
        p[i] = v;
        bf16 h = __float2bfloat16_rn(v);
        qhi[base + i] = h;
        qlo[base + i] = __float2bfloat16_rn(v - __bfloat162float(h));
    }
}

// ---------------------------------------------------------------------------
// S kernel: 3-pass bf16 split mma, triangular grid + mirror, fp16 store.
// ---------------------------------------------------------------------------
#define KC      64
#define PART_B  16384                  // 128 rows x 128 bytes
#define S_STAGE (4 * PART_B)           // qhiA qloA qhiB qloB
#define S_SMEM  (2 * S_STAGE)          // 128KB
#define TSTRIDE 136

__global__ __launch_bounds__(256, 1) void s_mma_kernel(
    const bf16* __restrict__ qhi, const bf16* __restrict__ qlo,
    const float* __restrict__ qn, half* __restrict__ S)
{
    extern __shared__ __align__(1024) char sm[];

    int tid = threadIdx.x;
    int wid = tid >> 5, lane = tid & 31;
    int wm = wid & 3, wn = wid >> 2;
    int bz = blockIdx.z;

    // triangular enumeration: t -> (by=j, bx=i), j<=i
    int t = blockIdx.x;
    int bi = (int)((sqrtf(8.0f * (float)t + 1.0f) - 1.0f) * 0.5f);
    while ((bi + 1) * (bi + 2) / 2 <= t) ++bi;
    while (bi * (bi + 1) / 2 > t) --bi;
    int by = t - bi * (bi + 1) / 2;
    int bx = bi;

    const bf16* Ah = qhi + (long)bz * SEQ * DIM + (long)by * 128 * DIM;
    const bf16* Al = qlo + (long)bz * SEQ * DIM + (long)by * 128 * DIM;
    const bf16* Bh = qhi + (long)bz * SEQ * DIM + (long)bx * 128 * DIM;
    const bf16* Bl = qlo + (long)bz * SEQ * DIM + (long)bx * 128 * DIM;

    uint32_t smb = smem_u32(sm);
    const int NC = DIM / KC;   // 8

    auto issue_chunk = [&](int c) {
        uint32_t st = smb + (uint32_t)(c & 1) * S_STAGE;
        int k0 = c * KC;
        const bf16* srcs[4] = { Ah, Al, Bh, Bl };
#pragma unroll
        for (int p = 0; p < 4; p++) {
#pragma unroll
            for (int i = 0; i < 4; i++) {
                int idx = tid + i * 256;
                int r = idx >> 3, c8 = idx & 7;
                uint32_t dst = st + (uint32_t)p * PART_B + (uint32_t)r * 128 + SWZC(c8 * 16, r);
                cp16(dst, srcs[p] + (long)r * DIM + k0 + c8 * 8);
            }
        }
        CP_COMMIT();
    };

    float acc[2][8][4];
#pragma unroll
    for (int mt = 0; mt < 2; mt++)
#pragma unroll
        for (int nt = 0; nt < 8; nt++)
#pragma unroll
            for (int i = 0; i < 4; i++) acc[mt][nt][i] = 0.0f;

    issue_chunk(0);

    for (int c = 0; c < NC; c++) {
        if (c + 1 < NC) { issue_chunk(c + 1); CP_WAIT(1); }
        else            { CP_WAIT(0); }
        __syncthreads();

        uint32_t base = smb + (uint32_t)(c & 1) * S_STAGE;
        uint32_t pAh = base, pAl = base + PART_B, pBh = base + 2 * PART_B, pBl = base + 3 * PART_B;

#pragma unroll
        for (int ks = 0; ks < 4; ks++) {
            uint32_t ah[2][4], al[2][4], bh[4][4], bl[4][4];
#pragma unroll
            for (int mt = 0; mt < 2; mt++) {
                int arow = wm * 32 + mt * 16 + (lane & 15);
                uint32_t off = (uint32_t)arow * 128 + SWZC(ks * 32 + (lane >> 4) * 16, arow);
                LDSM4(ah[mt][0], ah[mt][1], ah[mt][2], ah[mt][3], pAh + off);
                LDSM4(al[mt][0], al[mt][1], al[mt][2], al[mt][3], pAl + off);
            }
#pragma unroll
            for (int np = 0; np < 4; np++) {
                int brow = wn * 64 + np * 16 + (lane & 7) + ((lane >> 4) << 3);
                uint32_t off = (uint32_t)brow * 128 +
                               SWZC(ks * 32 + ((lane >> 3) & 1) * 16, brow);
                LDSM4(bh[np][0], bh[np][1], bh[np][2], bh[np][3], pBh + off);
                LDSM4(bl[np][0], bl[np][1], bl[np][2], bl[np][3], pBl + off);
            }
#pragma unroll
            for (int np = 0; np < 4; np++)
#pragma unroll
                for (int mt = 0; mt < 2; mt++) {
                    mma_bf(acc[mt][np * 2 + 0], ah[mt], bh[np] + 0);
                    mma_bf(acc[mt][np * 2 + 1], ah[mt], bh[np] + 2);
                }
#pragma unroll
            for (int np = 0; np < 4; np++)
#pragma unroll
                for (int mt = 0; mt < 2; mt++) {
                    mma_bf(acc[mt][np * 2 + 0], ah[mt], bl[np] + 0);
                    mma_bf(acc[mt][np * 2 + 1], ah[mt], bl[np] + 2);
                }
#pragma unroll
            for (int np = 0; np < 4; np++)
#pragma unroll
                for (int mt = 0; mt < 2; mt++) {
                    mma_bf(acc[mt][np * 2 + 0], al[mt], bh[np] + 0);
                    mma_bf(acc[mt][np * 2 + 1], al[mt], bh[np] + 2);
                }
        }
        __syncthreads();
    }

    // ---- epilogue: rescue + threshold + fp16 store (+ mirror) ----
    const float* qnB = qn + (long)bz * SEQ * DIM;
    half* smT = reinterpret_cast<half*>(sm);
    half* Sb = S + (long)bz * SEQ * SEQ;
    bool mirror = (bx != by);

#pragma unroll
    for (int mt = 0; mt < 2; mt++) {
#pragma unroll
        for (int hf = 0; hf < 2; hf++) {
            int lr = wm * 32 + mt * 16 + (lane >> 2) + hf * 8;
            int gr = by * 128 + lr;
            const float* qA = qnB + (long)gr * DIM;
#pragma unroll
            for (int nt = 0; nt < 8; nt++) {
                float s0 = acc[mt][nt][hf * 2 + 0];
                float s1 = acc[mt][nt][hf * 2 + 1];
                int ln0 = wn * 64 + nt * 8 + (lane & 3) * 2;
                int gn0 = bx * 128 + ln0;
                if (fabsf(s0 - EPS_THR) < BAND) {
                    const float* qB = qnB + (long)gn0 * DIM;
                    float a2 = 0.f;
#pragma unroll 8
                    for (int k = 0; k < DIM; k++) a2 = fmaf(qA[k], qB[k], a2);
                    s0 = a2;
                }
                if (fabsf(s1 - EPS_THR) < BAND) {
                    const float* qB = qnB + (long)(gn0 + 1) * DIM;
                    float a2 = 0.f;
#pragma unroll 8
                    for (int k = 0; k < DIM; k++) a2 = fmaf(qA[k], qB[k], a2);
                    s1 = a2;
                }
                s0 = (s0 > EPS_THR) ? s0 : 0.f;
                s1 = (s1 > EPS_THR) ? s1 : 0.f;
                half2 hh = __floats2half2_rn(s0, s1);
                *reinterpret_cast<half2*>(Sb + (long)gr * SEQ + gn0) = hh;
                if (mirror) {
                    smT[ln0 * TSTRIDE + lr]       = hh.x;
                    smT[(ln0 + 1) * TSTRIDE + lr] = hh.y;
                }
            }
        }
    }

    if (mirror) {
        __syncthreads();
        int r2 = tid >> 1, hs = tid & 1;
        const uint4* sr = reinterpret_cast<const uint4*>(smT + r2 * TSTRIDE + hs * 64);
        uint4* dh = reinterpret_cast<uint4*>(Sb + (long)(bx * 128 + r2) * SEQ + by * 128 + hs * 64);
#pragma unroll
        for (int g = 0; g < 8; g++) dh[g] = sr[g];
    }
}

// ---------------------------------------------------------------------------
// fp16 single-pass mma GEMM: C = A * B^T.
// STORE_HALF=0: fp32 store (AV).  STORE_HALF=1: fp16 store (v projection).
// ---------------------------------------------------------------------------
#define H_PART  16384                  // 128 rows x 128 bytes (64 fp16 k)
#define H_STAGE (2 * H_PART)           // A, B
#define H_SMEM  (2 * H_STAGE)          // 64KB

template<int STORE_HALF>
__global__ __launch_bounds__(256, 1) void h_mma_kernel(
    const half* __restrict__ A, long ldA, long sAb,
    const half* __restrict__ B, long ldB, long sBb,
    int K,
    float* __restrict__ Of, half* __restrict__ Oh, long ldO, long sOb)
{
    extern __shared__ __align__(1024) char sm[];

    int tid = threadIdx.x;
    int wid = tid >> 5, lane = tid & 31;
    int wm = wid & 3, wn = wid >> 2;
    int bx = blockIdx.x, by = blockIdx.y, bz = blockIdx.z;

    const half* At = A + (long)bz * sAb + (long)by * 128 * ldA;
    const half* Bt = B + (long)bz * sBb + (long)bx * 128 * ldB;

    uint32_t smb = smem_u32(sm);
    int NC = K / KC;

    auto issue_chunk = [&](int c) {
        uint32_t st = smb + (uint32_t)(c & 1) * H_STAGE;
        int k0 = c * KC;
        const half* srcs[2] = { At, Bt };
        long lds[2] = { ldA, ldB };
#pragma unroll
        for (int p = 0; p < 2; p++) {
#pragma unroll
            for (int i = 0; i < 4; i++) {
                int idx = tid + i * 256;
                int r = idx >> 3, c8 = idx & 7;
                uint32_t dst = st + (uint32_t)p * H_PART + (uint32_t)r * 128 + SWZC(c8 * 16, r);
                cp16(dst, srcs[p] + (long)r * lds[p] + k0 + c8 * 8);
            }
        }
        CP_COMMIT();
    };

    float acc[2][8][4];
#pragma unroll
    for (int mt = 0; mt < 2; mt++)
#pragma unroll
        for (int nt = 0; nt < 8; nt++)
#pragma unroll
            for (int i = 0; i < 4; i++) acc[mt][nt][i] = 0.0f;

    issue_chunk(0);

    for (int c = 0; c < NC; c++) {
        if (c + 1 < NC) { issue_chunk(c + 1); CP_WAIT(1); }
        else            { CP_WAIT(0); }
        __syncthreads();

        uint32_t base = smb + (uint32_t)(c & 1) * H_STAGE;
        uint32_t pA = base, pB = base + H_PART;

#pragma unroll
        for (int ks = 0; ks < 4; ks++) {
            uint32_t af[2][4], bf_[4][4];
#pragma unroll
            for (int mt = 0; mt < 2; mt++) {
                int arow = wm * 32 + mt * 16 + (lane & 15);
                uint32_t off = (uint32_t)arow * 128 + SWZC(ks * 32 + (lane >> 4) * 16, arow);
                LDSM4(af[mt][0], af[mt][1], af[mt][2], af[mt][3], pA + off);
            }
#pragma unroll
            for (int np = 0; np < 4; np++) {
                int brow = wn * 64 + np * 16 + (lane & 7) + ((lane >> 4) << 3);
                uint32_t off = (uint32_t)brow * 128 +
                               SWZC(ks * 32 + ((lane >> 3) & 1) * 16, brow);
                LDSM4(bf_[np][0], bf_[np][1], bf_[np][2], bf_[np][3], pB + off);
            }
#pragma unroll
            for (int np = 0; np < 4; np++)
#pragma unroll
                for (int mt = 0; mt < 2; mt++) {
                    mma_fp(acc[mt][np * 2 + 0], af[mt], bf_[np] + 0);
                    mma_fp(acc[mt][np * 2 + 1], af[mt], bf_[np] + 2);
                }
        }
        __syncthreads();
    }

    // ---- epilogue ----
#pragma unroll
    for (int mt = 0; mt < 2; mt++) {
#pragma unroll
        for (int hf = 0; hf < 2; hf++) {
            int gr = by * 128 + wm * 32 + mt * 16 + (lane >> 2) + hf * 8;
#pragma unroll
            for (int nt = 0; nt < 8; nt++) {
                int gn0 = bx * 128 + wn * 64 + nt * 8 + (lane & 3) * 2;
                long off = (long)bz * sOb + (long)gr * ldO + gn0;
                if (STORE_HALF) {
                    half2 h = __floats2half2_rn(acc[mt][nt][hf * 2 + 0],
                                                acc[mt][nt][hf * 2 + 1]);
                    *reinterpret_cast<half2*>(Oh + off) = h;
                } else {
                    float2 f2;
                    f2.x = acc[mt][nt][hf * 2 + 0];
                    f2.y = acc[mt][nt][hf * 2 + 1];
                    *reinterpret_cast<float2*>(Of + off) = f2;
                }
            }
        }
    }
}

// ---------------------------------------------------------------------------
// LayerNorm rows of out
// ---------------------------------------------------------------------------
__global__ __launch_bounds__(128) void layernorm_kernel(
    float* __restrict__ out, const float* __restrict__ gamma, const float* __restrict__ beta)
{
    float* p = out + (long)blockIdx.x * DIM;
    float s = 0.0f, s2 = 0.0f;
    float vals[4];
#pragma unroll
    for (int t = 0; t < 4; t++) {
        int i = threadIdx.x + t * 128;
        float v = p[i];
        vals[t] = v;
        s += v; s2 += v * v;
    }
    float mean   = block_reduce_sum_128(s)  * (1.0f / DIM);
    float meansq = block_reduce_sum_128(s2) * (1.0f / DIM);
    float var = meansq - mean * mean;
    float inv = rsqrtf(var + LN_EPS);
#pragma unroll
    for (int t = 0; t < 4; t++) {
        int i = threadIdx.x + t * 128;
        p[i] = (vals[t] - mean) * inv * gamma[i] + beta[i];
    }
}

// ---------------------------------------------------------------------------
// Launch
// ---------------------------------------------------------------------------
extern "C" void kernel_launch(void* const* d_in, const int* in_sizes, int n_in,
                              void* d_out, int out_size)
{
    const float* x     = (const float*)d_in[0];
    const float* W_qk  = (const float*)d_in[1];
    const float* W_v   = (const float*)d_in[2];
    const float* gamma = (const float*)d_in[3];
    const float* beta  = (const float*)d_in[4];
    float* out = (float*)d_out;

    float* qp;
    half *x16, *w16, *vt16, *s16;
    bf16 *qhi, *qlo;
    cudaGetSymbolAddress((void**)&qp,   g_q);
    cudaGetSymbolAddress((void**)&x16,  g_x16);
    cudaGetSymbolAddress((void**)&w16,  g_w16);
    cudaGetSymbolAddress((void**)&qhi,  g_qhi);
    cudaGetSymbolAddress((void**)&qlo,  g_qlo);
    cudaGetSymbolAddress((void**)&vt16, g_vt16);
    cudaGetSymbolAddress((void**)&s16,  g_s16);

    cudaFuncSetAttribute(s_mma_kernel, cudaFuncAttributeMaxDynamicSharedMemorySize, S_SMEM);
    cudaFuncSetAttribute(h_mma_kernel<0>, cudaFuncAttributeMaxDynamicSharedMemorySize, H_SMEM);
    cudaFuncSetAttribute(h_mma_kernel<1>, cudaFuncAttributeMaxDynamicSharedMemorySize, H_SMEM);

    // 1) q projection in fp32 (mask-critical path)
    {
        dim3 grid(DIM / BN, ROWS / BM, 1);
        gemm_abt_kernel<<<grid, 256>>>(x, W_qk, qp, ROWS, DIM, DIM);
    }

    // 2) fp16 conversions for the V path
    f2h_kernel<<<((long)ROWS * DIM / 4 + 255) / 256, 256>>>(x, x16, (long)ROWS * DIM);
    f2h_kernel<<<((long)DIM * DIM / 4 + 255) / 256, 256>>>(W_v, w16, (long)DIM * DIM);

    // 3) vT = W_v * x_b^T  (fp16 1-pass mma; output [DIM, SEQ] per batch)
    {
        dim3 grid(SEQ / 128, DIM / 128, BATCH);
        h_mma_kernel<1><<<grid, 256, H_SMEM>>>(
            w16, DIM, 0,
            x16, DIM, (long)SEQ * DIM,
            DIM,
            nullptr, vt16, SEQ, (long)DIM * SEQ);
    }

    // 4) L2-normalize q rows + bf16 hi/lo split
    l2norm_split_kernel<<<ROWS, 128>>>(qp, qhi, qlo);

    // 5) S = Qn*Qn^T — 3-pass bf16, triangular + mirror, fp16 store
    {
        int nt = SEQ / 128;
        dim3 grid(nt * (nt + 1) / 2, 1, BATCH);
        s_mma_kernel<<<grid, 256, S_SMEM>>>(qhi, qlo, qp, s16);
    }

    // 6) out = S * V  (fp16 1-pass mma, fp32 store)
    {
        dim3 grid(DIM / 128, SEQ / 128, BATCH);
        h_mma_kernel<0><<<grid, 256, H_SMEM>>>(
            s16, SEQ, (long)SEQ * SEQ,
            vt16, SEQ, (long)DIM * SEQ,
            SEQ,
            out, nullptr, DIM, (long)SEQ * DIM);
    }

    // 7) LayerNorm
    layernorm_kernel<<<ROWS, 128>>>(out, gamma, beta);
}

// round 7
// speedup vs baseline: 2.6696x; 1.1729x over previous
#include <cuda_runtime.h>
#include <cuda_bf16.h>
#include <cuda_fp16.h>
#include <cstdint>
#include <math.h>

// ---------------------------------------------------------------------------
// Problem constants
// ---------------------------------------------------------------------------
#define BATCH 4
#define SEQ   4096
#define DIM   512
#define ROWS  (BATCH * SEQ)          // 16384
#define EPS_THR 0.1f
#define BAND    4e-4f
#define LN_EPS  1e-5f
#define NORM_EPS 1e-12f

using bf16 = __nv_bfloat16;

// ---------------------------------------------------------------------------
// Scratch (__device__ globals; no runtime allocation)
// ---------------------------------------------------------------------------
__device__ float g_q   [(size_t)ROWS * DIM];          // fp32 q / qn
__device__ half  g_x16 [(size_t)ROWS * DIM];          // x fp16 (v path)
__device__ half  g_w16 [(size_t)DIM * DIM];           // W_v fp16
__device__ bf16  g_qhi [(size_t)ROWS * DIM];          // qn bf16 split
__device__ bf16  g_qlo [(size_t)ROWS * DIM];
__device__ half  g_vt16[(size_t)BATCH * DIM * SEQ];   // vT per batch [512,4096]
__device__ half  g_s16 [(size_t)BATCH * SEQ * SEQ];   // masked attn fp16

// ---------------------------------------------------------------------------
// PTX helpers (arch-agnostic: sm_80+)
// ---------------------------------------------------------------------------
__device__ __forceinline__ uint32_t smem_u32(const void* p) {
    uint32_t a;
    asm("{ .reg .u64 t; cvta.to.shared.u64 t, %1; cvt.u32.u64 %0, t; }"
        : "=r"(a) : "l"(p));
    return a;
}

__device__ __forceinline__ void cp16(uint32_t dst, const void* src) {
    asm volatile("cp.async.cg.shared.global [%0], [%1], 16;" :: "r"(dst), "l"(src));
}
#define CP_COMMIT() asm volatile("cp.async.commit_group;" ::: "memory")
#define CP_WAIT(n)  asm volatile("cp.async.wait_group %0;" :: "n"(n) : "memory")

#define LDSM4(r0, r1, r2, r3, addr) \
    asm volatile("ldmatrix.sync.aligned.m8n8.x4.shared.b16 {%0,%1,%2,%3},[%4];" \
                 : "=r"(r0), "=r"(r1), "=r"(r2), "=r"(r3) : "r"(addr))

__device__ __forceinline__ void mma_bf(float* c, const uint32_t* a, const uint32_t* b) {
    asm volatile(
        "mma.sync.aligned.m16n8k16.row.col.f32.bf16.bf16.f32 "
        "{%0,%1,%2,%3},{%4,%5,%6,%7},{%8,%9},{%0,%1,%2,%3};"
        : "+f"(c[0]), "+f"(c[1]), "+f"(c[2]), "+f"(c[3])
        : "r"(a[0]), "r"(a[1]), "r"(a[2]), "r"(a[3]), "r"(b[0]), "r"(b[1]));
}
__device__ __forceinline__ void mma_fp(float* c, const uint32_t* a, const uint32_t* b) {
    asm volatile(
        "mma.sync.aligned.m16n8k16.row.col.f32.f16.f16.f32 "
        "{%0,%1,%2,%3},{%4,%5,%6,%7},{%8,%9},{%0,%1,%2,%3};"
        : "+f"(c[0]), "+f"(c[1]), "+f"(c[2]), "+f"(c[3])
        : "r"(a[0]), "r"(a[1]), "r"(a[2]), "r"(a[3]), "r"(b[0]), "r"(b[1]));
}

#define SWZC(c, r) ((uint32_t)(c) ^ ((((uint32_t)(r)) & 7u) << 4))

#define KC      64
#define PART_B  16384                  // 128 rows x 128 bytes (64 x 16-bit k)
#define TSTRIDE 136

// ---------------------------------------------------------------------------
// fp32 SIMT projection GEMM (q only — mask-critical, must be fp32-exact)
// ---------------------------------------------------------------------------
#define BM 128
#define BN 128
#define BK 16
__global__ __launch_bounds__(256) void gemm_abt_kernel(
    const float* __restrict__ A, const float* __restrict__ B, float* __restrict__ C,
    int M, int N, int K)
{
    __shared__ float As[BK][BM + 4];
    __shared__ float Bs[BK][BN + 4];

    const float* Ab = A + (long)blockIdx.y * BM * K;
    const float* Bb = B + (long)blockIdx.x * BN * K;

    int tid = threadIdx.x;
    int tx = tid & 15, ty = tid >> 4;

    float acc[8][8];
#pragma unroll
    for (int i = 0; i < 8; i++)
#pragma unroll
        for (int j = 0; j < 8; j++) acc[i][j] = 0.0f;

    for (int k0 = 0; k0 < K; k0 += BK) {
#pragma unroll
        for (int i = 0; i < 8; i++) {
            int idx = tid + i * 256;
            int m = idx >> 4, kk = idx & 15;
            As[kk][m] = Ab[(long)m * K + k0 + kk];
            Bs[kk][m] = Bb[(long)m * K + k0 + kk];
        }
        __syncthreads();
#pragma unroll
        for (int kk = 0; kk < BK; kk++) {
            float a[8], b[8];
#pragma unroll
            for (int i = 0; i < 8; i++) a[i] = As[kk][ty * 8 + i];
#pragma unroll
            for (int j = 0; j < 8; j++) b[j] = Bs[kk][tx * 8 + j];
#pragma unroll
            for (int i = 0; i < 8; i++)
#pragma unroll
                for (int j = 0; j < 8; j++) acc[i][j] += a[i] * b[j];
        }
        __syncthreads();
    }

    int row0 = blockIdx.y * BM + ty * 8;
    int col0 = blockIdx.x * BN + tx * 8;
#pragma unroll
    for (int i = 0; i < 8; i++)
#pragma unroll
        for (int j = 0; j < 8; j++)
            C[(long)(row0 + i) * N + col0 + j] = acc[i][j];
}

// ---------------------------------------------------------------------------
// fp32 -> fp16 convert (n multiple of 4)
// ---------------------------------------------------------------------------
__global__ __launch_bounds__(256) void f2h_kernel(
    const float* __restrict__ src, half* __restrict__ dst, long n)
{
    long i = ((long)blockIdx.x * 256 + threadIdx.x) * 4;
    if (i < n) {
        float4 f = *reinterpret_cast<const float4*>(src + i);
        half2 h0 = __floats2half2_rn(f.x, f.y);
        half2 h1 = __floats2half2_rn(f.z, f.w);
        uint2 u;
        u.x = *reinterpret_cast<uint32_t*>(&h0);
        u.y = *reinterpret_cast<uint32_t*>(&h1);
        *reinterpret_cast<uint2*>(dst + i) = u;
    }
}

// ---------------------------------------------------------------------------
// Block reduce (128 threads)
// ---------------------------------------------------------------------------
__device__ __forceinline__ float block_reduce_sum_128(float v)
{
    __shared__ float sh[4];
#pragma unroll
    for (int o = 16; o > 0; o >>= 1) v += __shfl_down_sync(0xffffffffu, v, o);
    int lane = threadIdx.x & 31, w = threadIdx.x >> 5;
    if (lane == 0) sh[w] = v;
    __syncthreads();
    float total = sh[0] + sh[1] + sh[2] + sh[3];
    __syncthreads();
    return total;
}

__global__ __launch_bounds__(128) void l2norm_split_kernel(
    float* __restrict__ q, bf16* __restrict__ qhi, bf16* __restrict__ qlo)
{
    long base = (long)blockIdx.x * DIM;
    float* p = q + base;
    float s = 0.0f;
#pragma unroll
    for (int i = threadIdx.x; i < DIM; i += 128) { float v = p[i]; s += v * v; }
    float total = block_reduce_sum_128(s);
    float inv = 1.0f / fmaxf(sqrtf(total), NORM_EPS);
#pragma unroll
    for (int i = threadIdx.x; i < DIM; i += 128) {
        float v = p[i] * inv;
        p[i] = v;
        bf16 h = __float2bfloat16_rn(v);
        qhi[base + i] = h;
        qlo[base + i] = __float2bfloat16_rn(v - __bfloat162float(h));
    }
}

// ---------------------------------------------------------------------------
// S kernel: 3-pass bf16 split mma, 512 threads, 4x4 warps, 32x32 warp tile.
// Triangular grid + mirror; fp32 band rescue; fp16 store.
// ---------------------------------------------------------------------------
#define SP_STAGE (4 * PART_B)          // 64KB
#define SP_SMEM  (2 * SP_STAGE)        // 128KB

__global__ __launch_bounds__(512, 1) void s_mma_kernel(
    const bf16* __restrict__ qhi, const bf16* __restrict__ qlo,
    const float* __restrict__ qn, half* __restrict__ S)
{
    extern __shared__ __align__(1024) char sm[];

    int tid = threadIdx.x;
    int wid = tid >> 5, lane = tid & 31;
    int wm = wid & 3, wn = wid >> 2;          // 4 x 4 warp grid
    int bz = blockIdx.z;

    int t = blockIdx.x;
    int bi = (int)((sqrtf(8.0f * (float)t + 1.0f) - 1.0f) * 0.5f);
    while ((bi + 1) * (bi + 2) / 2 <= t) ++bi;
    while (bi * (bi + 1) / 2 > t) --bi;
    int by = t - bi * (bi + 1) / 2;
    int bx = bi;

    const bf16* Ah = qhi + (long)bz * SEQ * DIM + (long)by * 128 * DIM;
    const bf16* Al = qlo + (long)bz * SEQ * DIM + (long)by * 128 * DIM;
    const bf16* Bh = qhi + (long)bz * SEQ * DIM + (long)bx * 128 * DIM;
    const bf16* Bl = qlo + (long)bz * SEQ * DIM + (long)bx * 128 * DIM;

    uint32_t smb = smem_u32(sm);
    const int NC = DIM / KC;   // 8

    auto issue_chunk = [&](int c) {
        uint32_t st = smb + (uint32_t)(c & 1) * SP_STAGE;
        int k0 = c * KC;
        const bf16* srcs[4] = { Ah, Al, Bh, Bl };
#pragma unroll
        for (int p = 0; p < 4; p++) {
#pragma unroll
            for (int i = 0; i < 2; i++) {
                int idx = tid + i * 512;
                int r = idx >> 3, c8 = idx & 7;
                uint32_t dst = st + (uint32_t)p * PART_B + (uint32_t)r * 128 + SWZC(c8 * 16, r);
                cp16(dst, srcs[p] + (long)r * DIM + k0 + c8 * 8);
            }
        }
        CP_COMMIT();
    };

    float acc[2][4][4];
#pragma unroll
    for (int mt = 0; mt < 2; mt++)
#pragma unroll
        for (int nt = 0; nt < 4; nt++)
#pragma unroll
            for (int i = 0; i < 4; i++) acc[mt][nt][i] = 0.0f;

    issue_chunk(0);

    for (int c = 0; c < NC; c++) {
        if (c + 1 < NC) { issue_chunk(c + 1); CP_WAIT(1); }
        else            { CP_WAIT(0); }
        __syncthreads();

        uint32_t base = smb + (uint32_t)(c & 1) * SP_STAGE;
        uint32_t pAh = base, pAl = base + PART_B, pBh = base + 2 * PART_B, pBl = base + 3 * PART_B;

#pragma unroll
        for (int ks = 0; ks < 4; ks++) {
            uint32_t ah[2][4], al[2][4], bh[2][4], bl[2][4];
#pragma unroll
            for (int mt = 0; mt < 2; mt++) {
                int arow = wm * 32 + mt * 16 + (lane & 15);
                uint32_t off = (uint32_t)arow * 128 + SWZC(ks * 32 + (lane >> 4) * 16, arow);
                LDSM4(ah[mt][0], ah[mt][1], ah[mt][2], ah[mt][3], pAh + off);
                LDSM4(al[mt][0], al[mt][1], al[mt][2], al[mt][3], pAl + off);
            }
#pragma unroll
            for (int np = 0; np < 2; np++) {
                int brow = wn * 32 + np * 16 + (lane & 7) + ((lane >> 4) << 3);
                uint32_t off = (uint32_t)brow * 128 +
                               SWZC(ks * 32 + ((lane >> 3) & 1) * 16, brow);
                LDSM4(bh[np][0], bh[np][1], bh[np][2], bh[np][3], pBh + off);
                LDSM4(bl[np][0], bl[np][1], bl[np][2], bl[np][3], pBl + off);
            }
#pragma unroll
            for (int np = 0; np < 2; np++)
#pragma unroll
                for (int mt = 0; mt < 2; mt++) {
                    mma_bf(acc[mt][np * 2 + 0], ah[mt], bh[np] + 0);
                    mma_bf(acc[mt][np * 2 + 1], ah[mt], bh[np] + 2);
                }
#pragma unroll
            for (int np = 0; np < 2; np++)
#pragma unroll
                for (int mt = 0; mt < 2; mt++) {
                    mma_bf(acc[mt][np * 2 + 0], ah[mt], bl[np] + 0);
                    mma_bf(acc[mt][np * 2 + 1], ah[mt], bl[np] + 2);
                }
#pragma unroll
            for (int np = 0; np < 2; np++)
#pragma unroll
                for (int mt = 0; mt < 2; mt++) {
                    mma_bf(acc[mt][np * 2 + 0], al[mt], bh[np] + 0);
                    mma_bf(acc[mt][np * 2 + 1], al[mt], bh[np] + 2);
                }
        }
        __syncthreads();
    }

    // ---- epilogue: rescue + threshold + fp16 store (+ mirror) ----
    const float* qnB = qn + (long)bz * SEQ * DIM;
    half* smT = reinterpret_cast<half*>(sm);
    half* Sb = S + (long)bz * SEQ * SEQ;
    bool mirror = (bx != by);

#pragma unroll
    for (int mt = 0; mt < 2; mt++) {
#pragma unroll
        for (int hf = 0; hf < 2; hf++) {
            int lr = wm * 32 + mt * 16 + (lane >> 2) + hf * 8;
            int gr = by * 128 + lr;
            const float* qA = qnB + (long)gr * DIM;
#pragma unroll
            for (int nt = 0; nt < 4; nt++) {
                float s0 = acc[mt][nt][hf * 2 + 0];
                float s1 = acc[mt][nt][hf * 2 + 1];
                int ln0 = wn * 32 + nt * 8 + (lane & 3) * 2;
                int gn0 = bx * 128 + ln0;
                if (fabsf(s0 - EPS_THR) < BAND) {
                    const float* qB = qnB + (long)gn0 * DIM;
                    float a2 = 0.f;
#pragma unroll 8
                    for (int k = 0; k < DIM; k++) a2 = fmaf(qA[k], qB[k], a2);
                    s0 = a2;
                }
                if (fabsf(s1 - EPS_THR) < BAND) {
                    const float* qB = qnB + (long)(gn0 + 1) * DIM;
                    float a2 = 0.f;
#pragma unroll 8
                    for (int k = 0; k < DIM; k++) a2 = fmaf(qA[k], qB[k], a2);
                    s1 = a2;
                }
                s0 = (s0 > EPS_THR) ? s0 : 0.f;
                s1 = (s1 > EPS_THR) ? s1 : 0.f;
                half2 hh = __floats2half2_rn(s0, s1);
                *reinterpret_cast<half2*>(Sb + (long)gr * SEQ + gn0) = hh;
                if (mirror) {
                    smT[ln0 * TSTRIDE + lr]       = hh.x;
                    smT[(ln0 + 1) * TSTRIDE + lr] = hh.y;
                }
            }
        }
    }

    if (mirror) {
        __syncthreads();
        int r2 = tid >> 2;                   // 0..127
        int q4 = tid & 3;
#pragma unroll
        for (int g = 0; g < 4; g++) {
            int j = q4 + g * 4;              // uint4 index within row (16 per row)
            uint4 v = *reinterpret_cast<const uint4*>(smT + r2 * TSTRIDE + j * 8);
            *reinterpret_cast<uint4*>(Sb + (long)(bx * 128 + r2) * SEQ + by * 128 + j * 8) = v;
        }
    }
}

// ---------------------------------------------------------------------------
// fp16 single-pass mma GEMM: C = A * B^T.  512 threads, 4x4 warps.
// STORE_HALF=0: fp32 store (AV).  STORE_HALF=1: fp16 store (v projection).
// ---------------------------------------------------------------------------
#define H_STAGE (2 * PART_B)           // 32KB
#define H_SMEM  (2 * H_STAGE)          // 64KB

template<int STORE_HALF>
__global__ __launch_bounds__(512, 1) void h_mma_kernel(
    const half* __restrict__ A, long ldA, long sAb,
    const half* __restrict__ B, long ldB, long sBb,
    int K,
    float* __restrict__ Of, half* __restrict__ Oh, long ldO, long sOb)
{
    extern __shared__ __align__(1024) char sm[];

    int tid = threadIdx.x;
    int wid = tid >> 5, lane = tid & 31;
    int wm = wid & 3, wn = wid >> 2;
    int bx = blockIdx.x, by = blockIdx.y, bz = blockIdx.z;

    const half* At = A + (long)bz * sAb + (long)by * 128 * ldA;
    const half* Bt = B + (long)bz * sBb + (long)bx * 128 * ldB;

    uint32_t smb = smem_u32(sm);
    int NC = K / KC;

    auto issue_chunk = [&](int c) {
        uint32_t st = smb + (uint32_t)(c & 1) * H_STAGE;
        int k0 = c * KC;
        const half* srcs[2] = { At, Bt };
        long lds[2] = { ldA, ldB };
#pragma unroll
        for (int p = 0; p < 2; p++) {
#pragma unroll
            for (int i = 0; i < 2; i++) {
                int idx = tid + i * 512;
                int r = idx >> 3, c8 = idx & 7;
                uint32_t dst = st + (uint32_t)p * PART_B + (uint32_t)r * 128 + SWZC(c8 * 16, r);
                cp16(dst, srcs[p] + (long)r * lds[p] + k0 + c8 * 8);
            }
        }
        CP_COMMIT();
    };

    float acc[2][4][4];
#pragma unroll
    for (int mt = 0; mt < 2; mt++)
#pragma unroll
        for (int nt = 0; nt < 4; nt++)
#pragma unroll
            for (int i = 0; i < 4; i++) acc[mt][nt][i] = 0.0f;

    issue_chunk(0);

    for (int c = 0; c < NC; c++) {
        if (c + 1 < NC) { issue_chunk(c + 1); CP_WAIT(1); }
        else            { CP_WAIT(0); }
        __syncthreads();

        uint32_t base = smb + (uint32_t)(c & 1) * H_STAGE;
        uint32_t pA = base, pB = base + PART_B;

#pragma unroll
        for (int ks = 0; ks < 4; ks++) {
            uint32_t af[2][4], bfr[2][4];
#pragma unroll
            for (int mt = 0; mt < 2; mt++) {
                int arow = wm * 32 + mt * 16 + (lane & 15);
                uint32_t off = (uint32_t)arow * 128 + SWZC(ks * 32 + (lane >> 4) * 16, arow);
                LDSM4(af[mt][0], af[mt][1], af[mt][2], af[mt][3], pA + off);
            }
#pragma unroll
            for (int np = 0; np < 2; np++) {
                int brow = wn * 32 + np * 16 + (lane & 7) + ((lane >> 4) << 3);
                uint32_t off = (uint32_t)brow * 128 +
                               SWZC(ks * 32 + ((lane >> 3) & 1) * 16, brow);
                LDSM4(bfr[np][0], bfr[np][1], bfr[np][2], bfr[np][3], pB + off);
            }
#pragma unroll
            for (int np = 0; np < 2; np++)
#pragma unroll
                for (int mt = 0; mt < 2; mt++) {
                    mma_fp(acc[mt][np * 2 + 0], af[mt], bfr[np] + 0);
                    mma_fp(acc[mt][np * 2 + 1], af[mt], bfr[np] + 2);
                }
        }
        __syncthreads();
    }

#pragma unroll
    for (int mt = 0; mt < 2; mt++) {
#pragma unroll
        for (int hf = 0; hf < 2; hf++) {
            int gr = by * 128 + wm * 32 + mt * 16 + (lane >> 2) + hf * 8;
#pragma unroll
            for (int nt = 0; nt < 4; nt++) {
                int gn0 = bx * 128 + wn * 32 + nt * 8 + (lane & 3) * 2;
                long off = (long)bz * sOb + (long)gr * ldO + gn0;
                if (STORE_HALF) {
                    half2 h = __floats2half2_rn(acc[mt][nt][hf * 2 + 0],
                                                acc[mt][nt][hf * 2 + 1]);
                    *reinterpret_cast<half2*>(Oh + off) = h;
                } else {
                    float2 f2;
                    f2.x = acc[mt][nt][hf * 2 + 0];
                    f2.y = acc[mt][nt][hf * 2 + 1];
                    *reinterpret_cast<float2*>(Of + off) = f2;
                }
            }
        }
    }
}

// ---------------------------------------------------------------------------
// LayerNorm rows of out
// ---------------------------------------------------------------------------
__global__ __launch_bounds__(128) void layernorm_kernel(
    float* __restrict__ out, const float* __restrict__ gamma, const float* __restrict__ beta)
{
    float* p = out + (long)blockIdx.x * DIM;
    float s = 0.0f, s2 = 0.0f;
    float vals[4];
#pragma unroll
    for (int t = 0; t < 4; t++) {
        int i = threadIdx.x + t * 128;
        float v = p[i];
        vals[t] = v;
        s += v; s2 += v * v;
    }
    float mean   = block_reduce_sum_128(s)  * (1.0f / DIM);
    float meansq = block_reduce_sum_128(s2) * (1.0f / DIM);
    float var = meansq - mean * mean;
    float inv = rsqrtf(var + LN_EPS);
#pragma unroll
    for (int t = 0; t < 4; t++) {
        int i = threadIdx.x + t * 128;
        p[i] = (vals[t] - mean) * inv * gamma[i] + beta[i];
    }
}

// ---------------------------------------------------------------------------
// Launch
// ---------------------------------------------------------------------------
extern "C" void kernel_launch(void* const* d_in, const int* in_sizes, int n_in,
                              void* d_out, int out_size)
{
    const float* x     = (const float*)d_in[0];
    const float* W_qk  = (const float*)d_in[1];
    const float* W_v   = (const float*)d_in[2];
    const float* gamma = (const float*)d_in[3];
    const float* beta  = (const float*)d_in[4];
    float* out = (float*)d_out;

    float* qp;
    half *x16, *w16, *vt16, *s16;
    bf16 *qhi, *qlo;
    cudaGetSymbolAddress((void**)&qp,   g_q);
    cudaGetSymbolAddress((void**)&x16,  g_x16);
    cudaGetSymbolAddress((void**)&w16,  g_w16);
    cudaGetSymbolAddress((void**)&qhi,  g_qhi);
    cudaGetSymbolAddress((void**)&qlo,  g_qlo);
    cudaGetSymbolAddress((void**)&vt16, g_vt16);
    cudaGetSymbolAddress((void**)&s16,  g_s16);

    cudaFuncSetAttribute((const void*)s_mma_kernel, cudaFuncAttributeMaxDynamicSharedMemorySize, SP_SMEM);
    cudaFuncSetAttribute((const void*)h_mma_kernel<0>, cudaFuncAttributeMaxDynamicSharedMemorySize, H_SMEM);
    cudaFuncSetAttribute((const void*)h_mma_kernel<1>, cudaFuncAttributeMaxDynamicSharedMemorySize, H_SMEM);

    // 1) q projection in fp32 (mask-critical; MUST stay fp32-exact)
    {
        dim3 grid(DIM / BN, ROWS / BM, 1);
        gemm_abt_kernel<<<grid, 256>>>(x, W_qk, qp, ROWS, DIM, DIM);
    }

    // 2) fp16 conversions for the V path
    f2h_kernel<<<((long)ROWS * DIM / 4 + 255) / 256, 256>>>(x, x16, (long)ROWS * DIM);
    f2h_kernel<<<((long)DIM * DIM / 4 + 255) / 256, 256>>>(W_v, w16, (long)DIM * DIM);

    // 3) vT = W_v * x_b^T (fp16 1-pass; output [DIM, SEQ] per batch)
    {
        dim3 grid(SEQ / 128, DIM / 128, BATCH);
        h_mma_kernel<1><<<grid, 512, H_SMEM>>>(
            w16, DIM, 0,
            x16, DIM, (long)SEQ * DIM,
            DIM,
            nullptr, vt16, SEQ, (long)DIM * SEQ);
    }

    // 4) L2-normalize q rows + bf16 hi/lo split
    l2norm_split_kernel<<<ROWS, 128>>>(qp, qhi, qlo);

    // 5) S = Qn*Qn^T — 3-pass bf16, triangular + mirror, fp16 store
    {
        int nt = SEQ / 128;
        dim3 grid(nt * (nt + 1) / 2, 1, BATCH);
        s_mma_kernel<<<grid, 512, SP_SMEM>>>(qhi, qlo, qp, s16);
    }

    // 6) out = S * V (fp16 1-pass, fp32 store)
    {
        dim3 grid(DIM / 128, SEQ / 128, BATCH);
        h_mma_kernel<0><<<grid, 512, H_SMEM>>>(
            s16, SEQ, (long)SEQ * SEQ,
            vt16, SEQ, (long)DIM * SEQ,
            SEQ,
            out, nullptr, DIM, (long)SEQ * DIM);
    }

    // 7) LayerNorm
    layernorm_kernel<<<ROWS, 128>>>(out, gamma, beta);
}

// round 8
// speedup vs baseline: 2.9366x; 1.1000x over previous
#include <cuda_runtime.h>
#include <cuda_fp16.h>
#include <cstdint>
#include <math.h>

// ---------------------------------------------------------------------------
// Problem constants
// ---------------------------------------------------------------------------
#define BATCH 4
#define SEQ   4096
#define DIM   512
#define ROWS  (BATCH * SEQ)          // 16384
#define EPS_THR 0.1f
#define BAND    4e-4f
#define LN_EPS  1e-5f
#define NORM_EPS 1e-12f

// ---------------------------------------------------------------------------
// Scratch (__device__ globals; no runtime allocation)
// ---------------------------------------------------------------------------
__device__ float g_q   [(size_t)ROWS * DIM];          // fp32 q / qn
__device__ half  g_qn16[(size_t)ROWS * DIM];          // qn fp16
__device__ half  g_x16 [(size_t)ROWS * DIM];          // x fp16 (v path)
__device__ half  g_w16 [(size_t)DIM * DIM];           // W_v fp16
__device__ half  g_v16 [(size_t)ROWS * DIM];          // v fp16 row-major
__device__ half  g_s16 [(size_t)BATCH * SEQ * SEQ];   // masked attn fp16

// ---------------------------------------------------------------------------
// PTX helpers (arch-agnostic: sm_80+)
// ---------------------------------------------------------------------------
__device__ __forceinline__ uint32_t smem_u32(const void* p) {
    uint32_t a;
    asm("{ .reg .u64 t; cvta.to.shared.u64 t, %1; cvt.u32.u64 %0, t; }"
        : "=r"(a) : "l"(p));
    return a;
}

__device__ __forceinline__ void cp16(uint32_t dst, const void* src) {
    asm volatile("cp.async.cg.shared.global [%0], [%1], 16;" :: "r"(dst), "l"(src));
}
#define CP_COMMIT() asm volatile("cp.async.commit_group;" ::: "memory")
#define CP_WAIT(n)  asm volatile("cp.async.wait_group %0;" :: "n"(n) : "memory")

#define LDSM4(r0, r1, r2, r3, addr) \
    asm volatile("ldmatrix.sync.aligned.m8n8.x4.shared.b16 {%0,%1,%2,%3},[%4];" \
                 : "=r"(r0), "=r"(r1), "=r"(r2), "=r"(r3) : "r"(addr))

__device__ __forceinline__ void mma_fp(float* c, const uint32_t* a, const uint32_t* b) {
    asm volatile(
        "mma.sync.aligned.m16n8k16.row.col.f32.f16.f16.f32 "
        "{%0,%1,%2,%3},{%4,%5,%6,%7},{%8,%9},{%0,%1,%2,%3};"
        : "+f"(c[0]), "+f"(c[1]), "+f"(c[2]), "+f"(c[3])
        : "r"(a[0]), "r"(a[1]), "r"(a[2]), "r"(a[3]), "r"(b[0]), "r"(b[1]));
}

#define SWZC(c, r) ((uint32_t)(c) ^ ((((uint32_t)(r)) & 7u) << 4))

#define KC      64
#define PART_B  16384                  // 128 rows x 128 bytes (64 x 16-bit k)
#define TSTRIDE 136

// ---------------------------------------------------------------------------
// fp32 SIMT projection GEMM (q only — mask-critical, must be fp32-exact)
// ---------------------------------------------------------------------------
#define BM 128
#define BN 128
#define BK 16
__global__ __launch_bounds__(256) void gemm_abt_kernel(
    const float* __restrict__ A, const float* __restrict__ B, float* __restrict__ C,
    int M, int N, int K)
{
    __shared__ float As[BK][BM + 4];
    __shared__ float Bs[BK][BN + 4];

    const float* Ab = A + (long)blockIdx.y * BM * K;
    const float* Bb = B + (long)blockIdx.x * BN * K;

    int tid = threadIdx.x;
    int tx = tid & 15, ty = tid >> 4;

    float acc[8][8];
#pragma unroll
    for (int i = 0; i < 8; i++)
#pragma unroll
        for (int j = 0; j < 8; j++) acc[i][j] = 0.0f;

    for (int k0 = 0; k0 < K; k0 += BK) {
#pragma unroll
        for (int i = 0; i < 8; i++) {
            int idx = tid + i * 256;
            int m = idx >> 4, kk = idx & 15;
            As[kk][m] = Ab[(long)m * K + k0 + kk];
            Bs[kk][m] = Bb[(long)m * K + k0 + kk];
        }
        __syncthreads();
#pragma unroll
        for (int kk = 0; kk < BK; kk++) {
            float a[8], b[8];
#pragma unroll
            for (int i = 0; i < 8; i++) a[i] = As[kk][ty * 8 + i];
#pragma unroll
            for (int j = 0; j < 8; j++) b[j] = Bs[kk][tx * 8 + j];
#pragma unroll
            for (int i = 0; i < 8; i++)
#pragma unroll
                for (int j = 0; j < 8; j++) acc[i][j] += a[i] * b[j];
        }
        __syncthreads();
    }

    int row0 = blockIdx.y * BM + ty * 8;
    int col0 = blockIdx.x * BN + tx * 8;
#pragma unroll
    for (int i = 0; i < 8; i++)
#pragma unroll
        for (int j = 0; j < 8; j++)
            C[(long)(row0 + i) * N + col0 + j] = acc[i][j];
}

// ---------------------------------------------------------------------------
// fp32 -> fp16 convert (n multiple of 4)
// ---------------------------------------------------------------------------
__global__ __launch_bounds__(256) void f2h_kernel(
    const float* __restrict__ src, half* __restrict__ dst, long n)
{
    long i = ((long)blockIdx.x * 256 + threadIdx.x) * 4;
    if (i < n) {
        float4 f = *reinterpret_cast<const float4*>(src + i);
        half2 h0 = __floats2half2_rn(f.x, f.y);
        half2 h1 = __floats2half2_rn(f.z, f.w);
        uint2 u;
        u.x = *reinterpret_cast<uint32_t*>(&h0);
        u.y = *reinterpret_cast<uint32_t*>(&h1);
        *reinterpret_cast<uint2*>(dst + i) = u;
    }
}

// ---------------------------------------------------------------------------
// Block reduce (128 threads)
// ---------------------------------------------------------------------------
__device__ __forceinline__ float block_reduce_sum_128(float v)
{
    __shared__ float sh[4];
#pragma unroll
    for (int o = 16; o > 0; o >>= 1) v += __shfl_down_sync(0xffffffffu, v, o);
    int lane = threadIdx.x & 31, w = threadIdx.x >> 5;
    if (lane == 0) sh[w] = v;
    __syncthreads();
    float total = sh[0] + sh[1] + sh[2] + sh[3];
    __syncthreads();
    return total;
}

// L2-normalize q rows in place; emit fp16 plane
__global__ __launch_bounds__(128) void l2norm_kernel(
    float* __restrict__ q, half* __restrict__ q16)
{
    long base = (long)blockIdx.x * DIM;
    float* p = q + base;
    float s = 0.0f;
#pragma unroll
    for (int i = threadIdx.x; i < DIM; i += 128) { float v = p[i]; s += v * v; }
    float total = block_reduce_sum_128(s);
    float inv = 1.0f / fmaxf(sqrtf(total), NORM_EPS);
#pragma unroll
    for (int i = threadIdx.x; i < DIM; i += 128) {
        float v = p[i] * inv;
        p[i] = v;
        q16[base + i] = __float2half_rn(v);
    }
}

// ---------------------------------------------------------------------------
// S kernel: 1-pass fp16 mma, 512 threads 4x4 warps 32x32 tiles.
// Triangular grid + mirror; fp32 band rescue (band=26 sigma of fp16 dot error);
// fp16 store.
// ---------------------------------------------------------------------------
#define S1_STAGE (2 * PART_B)          // 32KB (A,B planes)
#define S1_SMEM  (2 * S1_STAGE)        // 64KB

__global__ __launch_bounds__(512, 1) void s_mma_kernel(
    const half* __restrict__ qn16, const float* __restrict__ qn,
    half* __restrict__ S)
{
    extern __shared__ __align__(1024) char sm[];

    int tid = threadIdx.x;
    int wid = tid >> 5, lane = tid & 31;
    int wm = wid & 3, wn = wid >> 2;
    int bz = blockIdx.z;

    int t = blockIdx.x;
    int bi = (int)((sqrtf(8.0f * (float)t + 1.0f) - 1.0f) * 0.5f);
    while ((bi + 1) * (bi + 2) / 2 <= t) ++bi;
    while (bi * (bi + 1) / 2 > t) --bi;
    int by = t - bi * (bi + 1) / 2;
    int bx = bi;

    const half* At = qn16 + (long)bz * SEQ * DIM + (long)by * 128 * DIM;
    const half* Bt = qn16 + (long)bz * SEQ * DIM + (long)bx * 128 * DIM;

    uint32_t smb = smem_u32(sm);
    const int NC = DIM / KC;   // 8

    auto issue_chunk = [&](int c) {
        uint32_t st = smb + (uint32_t)(c & 1) * S1_STAGE;
        int k0 = c * KC;
        const half* srcs[2] = { At, Bt };
#pragma unroll
        for (int p = 0; p < 2; p++) {
            int idx = tid;        // 512 threads cover 1024 lines in 2 steps
#pragma unroll
            for (int i = 0; i < 2; i++) {
                int r = (idx + i * 512) >> 3, c8 = (idx + i * 512) & 7;
                uint32_t dst = st + (uint32_t)p * PART_B + (uint32_t)r * 128 + SWZC(c8 * 16, r);
                cp16(dst, srcs[p] + (long)r * DIM + k0 + c8 * 8);
            }
        }
        CP_COMMIT();
    };

    float acc[2][4][4];
#pragma unroll
    for (int mt = 0; mt < 2; mt++)
#pragma unroll
        for (int nt = 0; nt < 4; nt++)
#pragma unroll
            for (int i = 0; i < 4; i++) acc[mt][nt][i] = 0.0f;

    issue_chunk(0);

    for (int c = 0; c < NC; c++) {
        if (c + 1 < NC) { issue_chunk(c + 1); CP_WAIT(1); }
        else            { CP_WAIT(0); }
        __syncthreads();

        uint32_t base = smb + (uint32_t)(c & 1) * S1_STAGE;
        uint32_t pA = base, pB = base + PART_B;

#pragma unroll
        for (int ks = 0; ks < 4; ks++) {
            uint32_t af[2][4], bfr[2][4];
#pragma unroll
            for (int mt = 0; mt < 2; mt++) {
                int arow = wm * 32 + mt * 16 + (lane & 15);
                uint32_t off = (uint32_t)arow * 128 + SWZC(ks * 32 + (lane >> 4) * 16, arow);
                LDSM4(af[mt][0], af[mt][1], af[mt][2], af[mt][3], pA + off);
            }
#pragma unroll
            for (int np = 0; np < 2; np++) {
                int brow = wn * 32 + np * 16 + (lane & 7) + ((lane >> 4) << 3);
                uint32_t off = (uint32_t)brow * 128 +
                               SWZC(ks * 32 + ((lane >> 3) & 1) * 16, brow);
                LDSM4(bfr[np][0], bfr[np][1], bfr[np][2], bfr[np][3], pB + off);
            }
#pragma unroll
            for (int np = 0; np < 2; np++)
#pragma unroll
                for (int mt = 0; mt < 2; mt++) {
                    mma_fp(acc[mt][np * 2 + 0], af[mt], bfr[np] + 0);
                    mma_fp(acc[mt][np * 2 + 1], af[mt], bfr[np] + 2);
                }
        }
        __syncthreads();
    }

    // ---- epilogue: rescue + threshold + fp16 store (+ mirror) ----
    const float* qnB = qn + (long)bz * SEQ * DIM;
    half* smT = reinterpret_cast<half*>(sm);
    half* Sb = S + (long)bz * SEQ * SEQ;
    bool mirror = (bx != by);

#pragma unroll
    for (int mt = 0; mt < 2; mt++) {
#pragma unroll
        for (int hf = 0; hf < 2; hf++) {
            int lr = wm * 32 + mt * 16 + (lane >> 2) + hf * 8;
            int gr = by * 128 + lr;
            const float* qA = qnB + (long)gr * DIM;
#pragma unroll
            for (int nt = 0; nt < 4; nt++) {
                float s0 = acc[mt][nt][hf * 2 + 0];
                float s1 = acc[mt][nt][hf * 2 + 1];
                int ln0 = wn * 32 + nt * 8 + (lane & 3) * 2;
                int gn0 = bx * 128 + ln0;
                if (fabsf(s0 - EPS_THR) < BAND) {
                    const float* qB = qnB + (long)gn0 * DIM;
                    float a2 = 0.f;
#pragma unroll 8
                    for (int k = 0; k < DIM; k++) a2 = fmaf(qA[k], qB[k], a2);
                    s0 = a2;
                }
                if (fabsf(s1 - EPS_THR) < BAND) {
                    const float* qB = qnB + (long)(gn0 + 1) * DIM;
                    float a2 = 0.f;
#pragma unroll 8
                    for (int k = 0; k < DIM; k++) a2 = fmaf(qA[k], qB[k], a2);
                    s1 = a2;
                }
                s0 = (s0 > EPS_THR) ? s0 : 0.f;
                s1 = (s1 > EPS_THR) ? s1 : 0.f;
                half2 hh = __floats2half2_rn(s0, s1);
                *reinterpret_cast<half2*>(Sb + (long)gr * SEQ + gn0) = hh;
                if (mirror) {
                    smT[ln0 * TSTRIDE + lr]       = hh.x;
                    smT[(ln0 + 1) * TSTRIDE + lr] = hh.y;
                }
            }
        }
    }

    if (mirror) {
        __syncthreads();
        int r2 = tid >> 2;
        int q4 = tid & 3;
#pragma unroll
        for (int g = 0; g < 4; g++) {
            int j = q4 + g * 4;
            uint4 v = *reinterpret_cast<const uint4*>(smT + r2 * TSTRIDE + j * 8);
            *reinterpret_cast<uint4*>(Sb + (long)(bx * 128 + r2) * SEQ + by * 128 + j * 8) = v;
        }
    }
}

// ---------------------------------------------------------------------------
// fp16 1-pass mma GEMM, fp16 store: used for v = x * W_v^T (row-major out)
// ---------------------------------------------------------------------------
#define H_STAGE (2 * PART_B)
#define H_SMEM  (2 * H_STAGE)

__global__ __launch_bounds__(512, 1) void h_mma_kernel(
    const half* __restrict__ A, long ldA,
    const half* __restrict__ B, long ldB,
    int K, half* __restrict__ Oh, long ldO)
{
    extern __shared__ __align__(1024) char sm[];

    int tid = threadIdx.x;
    int wid = tid >> 5, lane = tid & 31;
    int wm = wid & 3, wn = wid >> 2;
    int bx = blockIdx.x, by = blockIdx.y;

    const half* At = A + (long)by * 128 * ldA;
    const half* Bt = B + (long)bx * 128 * ldB;

    uint32_t smb = smem_u32(sm);
    int NC = K / KC;

    auto issue_chunk = [&](int c) {
        uint32_t st = smb + (uint32_t)(c & 1) * H_STAGE;
        int k0 = c * KC;
        const half* srcs[2] = { At, Bt };
        long lds[2] = { ldA, ldB };
#pragma unroll
        for (int p = 0; p < 2; p++) {
#pragma unroll
            for (int i = 0; i < 2; i++) {
                int idx = tid + i * 512;
                int r = idx >> 3, c8 = idx & 7;
                uint32_t dst = st + (uint32_t)p * PART_B + (uint32_t)r * 128 + SWZC(c8 * 16, r);
                cp16(dst, srcs[p] + (long)r * lds[p] + k0 + c8 * 8);
            }
        }
        CP_COMMIT();
    };

    float acc[2][4][4];
#pragma unroll
    for (int mt = 0; mt < 2; mt++)
#pragma unroll
        for (int nt = 0; nt < 4; nt++)
#pragma unroll
            for (int i = 0; i < 4; i++) acc[mt][nt][i] = 0.0f;

    issue_chunk(0);

    for (int c = 0; c < NC; c++) {
        if (c + 1 < NC) { issue_chunk(c + 1); CP_WAIT(1); }
        else            { CP_WAIT(0); }
        __syncthreads();

        uint32_t base = smb + (uint32_t)(c & 1) * H_STAGE;
        uint32_t pA = base, pB = base + PART_B;

#pragma unroll
        for (int ks = 0; ks < 4; ks++) {
            uint32_t af[2][4], bfr[2][4];
#pragma unroll
            for (int mt = 0; mt < 2; mt++) {
                int arow = wm * 32 + mt * 16 + (lane & 15);
                uint32_t off = (uint32_t)arow * 128 + SWZC(ks * 32 + (lane >> 4) * 16, arow);
                LDSM4(af[mt][0], af[mt][1], af[mt][2], af[mt][3], pA + off);
            }
#pragma unroll
            for (int np = 0; np < 2; np++) {
                int brow = wn * 32 + np * 16 + (lane & 7) + ((lane >> 4) << 3);
                uint32_t off = (uint32_t)brow * 128 +
                               SWZC(ks * 32 + ((lane >> 3) & 1) * 16, brow);
                LDSM4(bfr[np][0], bfr[np][1], bfr[np][2], bfr[np][3], pB + off);
            }
#pragma unroll
            for (int np = 0; np < 2; np++)
#pragma unroll
                for (int mt = 0; mt < 2; mt++) {
                    mma_fp(acc[mt][np * 2 + 0], af[mt], bfr[np] + 0);
                    mma_fp(acc[mt][np * 2 + 1], af[mt], bfr[np] + 2);
                }
        }
        __syncthreads();
    }

#pragma unroll
    for (int mt = 0; mt < 2; mt++) {
#pragma unroll
        for (int hf = 0; hf < 2; hf++) {
            int gr = by * 128 + wm * 32 + mt * 16 + (lane >> 2) + hf * 8;
#pragma unroll
            for (int nt = 0; nt < 4; nt++) {
                int gn0 = bx * 128 + wn * 32 + nt * 8 + (lane & 3) * 2;
                half2 h = __floats2half2_rn(acc[mt][nt][hf * 2 + 0],
                                            acc[mt][nt][hf * 2 + 1]);
                *reinterpret_cast<half2*>(Oh + (long)gr * ldO + gn0) = h;
            }
        }
    }
}

// ---------------------------------------------------------------------------
// Sparse A*V + fused LayerNorm.
// One block (128 threads) per output row. Scans the fp16 S row in chunks,
// compacts nonzeros deterministically (prefix-sum order = column order),
// gathers V rows (L2-resident), LayerNorms in-register, writes final out.
// ---------------------------------------------------------------------------
__global__ __launch_bounds__(128) void av_ln_kernel(
    const half* __restrict__ S, const half* __restrict__ V,
    const float* __restrict__ gamma, const float* __restrict__ beta,
    float* __restrict__ out)
{
    int gr = blockIdx.x;                 // 0..ROWS-1
    int bz = gr >> 12;                   // / SEQ
    int n  = gr & (SEQ - 1);
    const half* Srow = S + ((long)bz * SEQ + n) * SEQ;
    const half* Vb   = V + (long)bz * SEQ * DIM;
    int tid = threadIdx.x, lane = tid & 31, wrp = tid >> 5;

    __shared__ int   s_idx[1024];
    __shared__ float s_val[1024];
    __shared__ int   s_wbase[4];

    float a0 = 0.f, a1 = 0.f, a2 = 0.f, a3 = 0.f;

#pragma unroll 1
    for (int ch = 0; ch < SEQ / 1024; ch++) {
        // scan: thread owns 8 consecutive halves
        uint4 w = *reinterpret_cast<const uint4*>(Srow + ch * 1024 + tid * 8);
        uint32_t ws[4] = { w.x, w.y, w.z, w.w };
        uint16_t hs[8];
#pragma unroll
        for (int k = 0; k < 4; k++) {
            hs[2 * k]     = (uint16_t)(ws[k] & 0xFFFFu);
            hs[2 * k + 1] = (uint16_t)(ws[k] >> 16);
        }
        int nz = 0;
#pragma unroll
        for (int k = 0; k < 8; k++) nz += (hs[k] != 0);

        // deterministic block-wide exclusive offset (column order)
        int inc = nz;
#pragma unroll
        for (int o = 1; o < 32; o <<= 1) {
            int vsh = __shfl_up_sync(0xffffffffu, inc, o);
            if (lane >= o) inc += vsh;
        }
        if (lane == 31) s_wbase[wrp] = inc;
        __syncthreads();
        int wb = 0;
#pragma unroll
        for (int ww = 0; ww < 4; ww++) if (ww < wrp) wb += s_wbase[ww];
        int total = s_wbase[0] + s_wbase[1] + s_wbase[2] + s_wbase[3];
        int pos = wb + inc - nz;
#pragma unroll
        for (int k = 0; k < 8; k++) {
            if (hs[k] != 0) {
                __half_raw hr; hr.x = hs[k];
                s_idx[pos] = ch * 1024 + tid * 8 + k;
                s_val[pos] = __half2float((half)hr);
                pos++;
            }
        }
        __syncthreads();

        // drain: gather V rows
        for (int i = 0; i < total; i++) {
            float sv = s_val[i];
            int m = s_idx[i];
            uint2 vv = *reinterpret_cast<const uint2*>(Vb + (long)m * DIM + tid * 4);
            half2 h0 = *reinterpret_cast<half2*>(&vv.x);
            half2 h1 = *reinterpret_cast<half2*>(&vv.y);
            float2 f0 = __half22float2(h0);
            float2 f1 = __half22float2(h1);
            a0 = fmaf(sv, f0.x, a0);
            a1 = fmaf(sv, f0.y, a1);
            a2 = fmaf(sv, f1.x, a2);
            a3 = fmaf(sv, f1.y, a3);
        }
        __syncthreads();
    }

    // fused LayerNorm over 512 values (4 per thread)
    float s1 = a0 + a1 + a2 + a3;
    float s2 = a0 * a0 + a1 * a1 + a2 * a2 + a3 * a3;
    float ts1 = block_reduce_sum_128(s1);
    float ts2 = block_reduce_sum_128(s2);
    float mean = ts1 * (1.0f / DIM);
    float var  = ts2 * (1.0f / DIM) - mean * mean;
    float inv = rsqrtf(var + LN_EPS);

    float4 g = *reinterpret_cast<const float4*>(gamma + tid * 4);
    float4 b = *reinterpret_cast<const float4*>(beta + tid * 4);
    float4 o;
    o.x = (a0 - mean) * inv * g.x + b.x;
    o.y = (a1 - mean) * inv * g.y + b.y;
    o.z = (a2 - mean) * inv * g.z + b.z;
    o.w = (a3 - mean) * inv * g.w + b.w;
    *reinterpret_cast<float4*>(out + (long)gr * DIM + tid * 4) = o;
}

// ---------------------------------------------------------------------------
// Launch
// ---------------------------------------------------------------------------
extern "C" void kernel_launch(void* const* d_in, const int* in_sizes, int n_in,
                              void* d_out, int out_size)
{
    const float* x     = (const float*)d_in[0];
    const float* W_qk  = (const float*)d_in[1];
    const float* W_v   = (const float*)d_in[2];
    const float* gamma = (const float*)d_in[3];
    const float* beta  = (const float*)d_in[4];
    float* out = (float*)d_out;

    float* qp;
    half *qn16, *x16, *w16, *v16, *s16;
    cudaGetSymbolAddress((void**)&qp,   g_q);
    cudaGetSymbolAddress((void**)&qn16, g_qn16);
    cudaGetSymbolAddress((void**)&x16,  g_x16);
    cudaGetSymbolAddress((void**)&w16,  g_w16);
    cudaGetSymbolAddress((void**)&v16,  g_v16);
    cudaGetSymbolAddress((void**)&s16,  g_s16);

    cudaFuncSetAttribute((const void*)s_mma_kernel, cudaFuncAttributeMaxDynamicSharedMemorySize, S1_SMEM);
    cudaFuncSetAttribute((const void*)h_mma_kernel, cudaFuncAttributeMaxDynamicSharedMemorySize, H_SMEM);

    // 1) q projection in fp32 (mask-critical; MUST stay fp32-exact)
    {
        dim3 grid(DIM / BN, ROWS / BM, 1);
        gemm_abt_kernel<<<grid, 256>>>(x, W_qk, qp, ROWS, DIM, DIM);
    }

    // 2) fp16 conversions for the V path
    f2h_kernel<<<((long)ROWS * DIM / 4 + 255) / 256, 256>>>(x, x16, (long)ROWS * DIM);
    f2h_kernel<<<((long)DIM * DIM / 4 + 255) / 256, 256>>>(W_v, w16, (long)DIM * DIM);

    // 3) v = x * W_v^T (fp16 1-pass; row-major [ROWS, DIM] — no transpose)
    {
        dim3 grid(DIM / 128, ROWS / 128, 1);
        h_mma_kernel<<<grid, 512, H_SMEM>>>(x16, DIM, w16, DIM, DIM, v16, DIM);
    }

    // 4) L2-normalize q rows + fp16 plane
    l2norm_kernel<<<ROWS, 128>>>(qp, qn16);

    // 5) S = Qn*Qn^T — 1-pass fp16, triangular + mirror, rescue, fp16 store
    {
        int nt = SEQ / 128;
        dim3 grid(nt * (nt + 1) / 2, 1, BATCH);
        s_mma_kernel<<<grid, 512, S1_SMEM>>>(qn16, qp, s16);
    }

    // 6) out = LayerNorm(S * V) — sparse gather, fused LN
    av_ln_kernel<<<ROWS, 128>>>(s16, v16, gamma, beta, out);
}

// round 9
// speedup vs baseline: 5.0170x; 1.7084x over previous
#include <cuda_runtime.h>
#include <cuda_fp16.h>
#include <cstdint>
#include <math.h>

// ---------------------------------------------------------------------------
// Problem constants
// ---------------------------------------------------------------------------
#define BATCH 4
#define SEQ   4096
#define DIM   512
#define ROWS  (BATCH * SEQ)          // 16384
#define EPS_THR 0.1f
#define BAND    4e-4f
#define LN_EPS  1e-5f
#define NORM_EPS 1e-12f

// ---------------------------------------------------------------------------
// Scratch (__device__ globals; no runtime allocation)
// ---------------------------------------------------------------------------
__device__ float g_q   [(size_t)ROWS * DIM];          // fp32 q / qn
__device__ half  g_qn16[(size_t)ROWS * DIM];          // qn fp16
__device__ half  g_x16 [(size_t)ROWS * DIM];          // x fp16 (v path)
__device__ half  g_w16 [(size_t)DIM * DIM];           // W_v fp16
__device__ half  g_v16 [(size_t)ROWS * DIM];          // v fp16 row-major
__device__ half  g_s16 [(size_t)BATCH * SEQ * SEQ];   // masked attn fp16

// ---------------------------------------------------------------------------
// PTX helpers (arch-agnostic: sm_80+)
// ---------------------------------------------------------------------------
__device__ __forceinline__ uint32_t smem_u32(const void* p) {
    uint32_t a;
    asm("{ .reg .u64 t; cvta.to.shared.u64 t, %1; cvt.u32.u64 %0, t; }"
        : "=r"(a) : "l"(p));
    return a;
}

__device__ __forceinline__ void cp16(uint32_t dst, const void* src) {
    asm volatile("cp.async.cg.shared.global [%0], [%1], 16;" :: "r"(dst), "l"(src));
}
#define CP_COMMIT() asm volatile("cp.async.commit_group;" ::: "memory")
#define CP_WAIT(n)  asm volatile("cp.async.wait_group %0;" :: "n"(n) : "memory")

#define LDSM4(r0, r1, r2, r3, addr) \
    asm volatile("ldmatrix.sync.aligned.m8n8.x4.shared.b16 {%0,%1,%2,%3},[%4];" \
                 : "=r"(r0), "=r"(r1), "=r"(r2), "=r"(r3) : "r"(addr))

__device__ __forceinline__ void mma_fp(float* c, const uint32_t* a, const uint32_t* b) {
    asm volatile(
        "mma.sync.aligned.m16n8k16.row.col.f32.f16.f16.f32 "
        "{%0,%1,%2,%3},{%4,%5,%6,%7},{%8,%9},{%0,%1,%2,%3};"
        : "+f"(c[0]), "+f"(c[1]), "+f"(c[2]), "+f"(c[3])
        : "r"(a[0]), "r"(a[1]), "r"(a[2]), "r"(a[3]), "r"(b[0]), "r"(b[1]));
}

#define SWZC(c, r) ((uint32_t)(c) ^ ((((uint32_t)(r)) & 7u) << 4))

#define KC      64
#define PART_B  16384                  // 128 rows x 128 bytes (64 x 16-bit k)
#define TSTRIDE 136

// ---------------------------------------------------------------------------
// fp32 SIMT projection GEMM (q only — mask-critical, must be fp32-exact)
// ---------------------------------------------------------------------------
#define BM 128
#define BN 128
#define BK 16
__global__ __launch_bounds__(256) void gemm_abt_kernel(
    const float* __restrict__ A, const float* __restrict__ B, float* __restrict__ C,
    int M, int N, int K)
{
    __shared__ float As[BK][BM + 4];
    __shared__ float Bs[BK][BN + 4];

    const float* Ab = A + (long)blockIdx.y * BM * K;
    const float* Bb = B + (long)blockIdx.x * BN * K;

    int tid = threadIdx.x;
    int tx = tid & 15, ty = tid >> 4;

    float acc[8][8];
#pragma unroll
    for (int i = 0; i < 8; i++)
#pragma unroll
        for (int j = 0; j < 8; j++) acc[i][j] = 0.0f;

    for (int k0 = 0; k0 < K; k0 += BK) {
#pragma unroll
        for (int i = 0; i < 8; i++) {
            int idx = tid + i * 256;
            int m = idx >> 4, kk = idx & 15;
            As[kk][m] = Ab[(long)m * K + k0 + kk];
            Bs[kk][m] = Bb[(long)m * K + k0 + kk];
        }
        __syncthreads();
#pragma unroll
        for (int kk = 0; kk < BK; kk++) {
            float a[8], b[8];
#pragma unroll
            for (int i = 0; i < 8; i++) a[i] = As[kk][ty * 8 + i];
#pragma unroll
            for (int j = 0; j < 8; j++) b[j] = Bs[kk][tx * 8 + j];
#pragma unroll
            for (int i = 0; i < 8; i++)
#pragma unroll
                for (int j = 0; j < 8; j++) acc[i][j] += a[i] * b[j];
        }
        __syncthreads();
    }

    int row0 = blockIdx.y * BM + ty * 8;
    int col0 = blockIdx.x * BN + tx * 8;
#pragma unroll
    for (int i = 0; i < 8; i++)
#pragma unroll
        for (int j = 0; j < 8; j++)
            C[(long)(row0 + i) * N + col0 + j] = acc[i][j];
}

// ---------------------------------------------------------------------------
// fp32 -> fp16 convert (n multiple of 4)
// ---------------------------------------------------------------------------
__global__ __launch_bounds__(256) void f2h_kernel(
    const float* __restrict__ src, half* __restrict__ dst, long n)
{
    long i = ((long)blockIdx.x * 256 + threadIdx.x) * 4;
    if (i < n) {
        float4 f = *reinterpret_cast<const float4*>(src + i);
        half2 h0 = __floats2half2_rn(f.x, f.y);
        half2 h1 = __floats2half2_rn(f.z, f.w);
        uint2 u;
        u.x = *reinterpret_cast<uint32_t*>(&h0);
        u.y = *reinterpret_cast<uint32_t*>(&h1);
        *reinterpret_cast<uint2*>(dst + i) = u;
    }
}

// ---------------------------------------------------------------------------
// Block reduce (128 threads)
// ---------------------------------------------------------------------------
__device__ __forceinline__ float block_reduce_sum_128(float v)
{
    __shared__ float sh[4];
#pragma unroll
    for (int o = 16; o > 0; o >>= 1) v += __shfl_down_sync(0xffffffffu, v, o);
    int lane = threadIdx.x & 31, w = threadIdx.x >> 5;
    if (lane == 0) sh[w] = v;
    __syncthreads();
    float total = sh[0] + sh[1] + sh[2] + sh[3];
    __syncthreads();
    return total;
}

// L2-normalize q rows in place; emit fp16 plane
__global__ __launch_bounds__(128) void l2norm_kernel(
    float* __restrict__ q, half* __restrict__ q16)
{
    long base = (long)blockIdx.x * DIM;
    float* p = q + base;
    float s = 0.0f;
#pragma unroll
    for (int i = threadIdx.x; i < DIM; i += 128) { float v = p[i]; s += v * v; }
    float total = block_reduce_sum_128(s);
    float inv = 1.0f / fmaxf(sqrtf(total), NORM_EPS);
#pragma unroll
    for (int i = threadIdx.x; i < DIM; i += 128) {
        float v = p[i] * inv;
        p[i] = v;
        q16[base + i] = __float2half_rn(v);
    }
}

// ---------------------------------------------------------------------------
// S kernel: 1-pass fp16 mma, 512 threads 4x4 warps 32x32 tiles.
// Triangular grid + mirror; WARP-COOPERATIVE fp32 band rescue; fp16 store.
// ---------------------------------------------------------------------------
#define S1_STAGE (2 * PART_B)          // 32KB (A,B planes)
#define S1_SMEM  (2 * S1_STAGE)        // 64KB
#define RMAX 512

__global__ __launch_bounds__(512, 1) void s_mma_kernel(
    const half* __restrict__ qn16, const float* __restrict__ qn,
    half* __restrict__ S)
{
    extern __shared__ __align__(1024) char sm[];
    __shared__ int rcount;
    __shared__ unsigned short rlist[RMAX];

    int tid = threadIdx.x;
    int wid = tid >> 5, lane = tid & 31;
    int wm = wid & 3, wn = wid >> 2;
    int bz = blockIdx.z;

    int t = blockIdx.x;
    int bi = (int)((sqrtf(8.0f * (float)t + 1.0f) - 1.0f) * 0.5f);
    while ((bi + 1) * (bi + 2) / 2 <= t) ++bi;
    while (bi * (bi + 1) / 2 > t) --bi;
    int by = t - bi * (bi + 1) / 2;
    int bx = bi;

    const half* At = qn16 + (long)bz * SEQ * DIM + (long)by * 128 * DIM;
    const half* Bt = qn16 + (long)bz * SEQ * DIM + (long)bx * 128 * DIM;

    uint32_t smb = smem_u32(sm);
    const int NC = DIM / KC;   // 8

    auto issue_chunk = [&](int c) {
        uint32_t st = smb + (uint32_t)(c & 1) * S1_STAGE;
        int k0 = c * KC;
        const half* srcs[2] = { At, Bt };
#pragma unroll
        for (int p = 0; p < 2; p++) {
#pragma unroll
            for (int i = 0; i < 2; i++) {
                int idx = tid + i * 512;
                int r = idx >> 3, c8 = idx & 7;
                uint32_t dst = st + (uint32_t)p * PART_B + (uint32_t)r * 128 + SWZC(c8 * 16, r);
                cp16(dst, srcs[p] + (long)r * DIM + k0 + c8 * 8);
            }
        }
        CP_COMMIT();
    };

    if (tid == 0) rcount = 0;

    float acc[2][4][4];
#pragma unroll
    for (int mt = 0; mt < 2; mt++)
#pragma unroll
        for (int nt = 0; nt < 4; nt++)
#pragma unroll
            for (int i = 0; i < 4; i++) acc[mt][nt][i] = 0.0f;

    issue_chunk(0);

    for (int c = 0; c < NC; c++) {
        if (c + 1 < NC) { issue_chunk(c + 1); CP_WAIT(1); }
        else            { CP_WAIT(0); }
        __syncthreads();

        uint32_t base = smb + (uint32_t)(c & 1) * S1_STAGE;
        uint32_t pA = base, pB = base + PART_B;

#pragma unroll
        for (int ks = 0; ks < 4; ks++) {
            uint32_t af[2][4], bfr[2][4];
#pragma unroll
            for (int mt = 0; mt < 2; mt++) {
                int arow = wm * 32 + mt * 16 + (lane & 15);
                uint32_t off = (uint32_t)arow * 128 + SWZC(ks * 32 + (lane >> 4) * 16, arow);
                LDSM4(af[mt][0], af[mt][1], af[mt][2], af[mt][3], pA + off);
            }
#pragma unroll
            for (int np = 0; np < 2; np++) {
                int brow = wn * 32 + np * 16 + (lane & 7) + ((lane >> 4) << 3);
                uint32_t off = (uint32_t)brow * 128 +
                               SWZC(ks * 32 + ((lane >> 3) & 1) * 16, brow);
                LDSM4(bfr[np][0], bfr[np][1], bfr[np][2], bfr[np][3], pB + off);
            }
#pragma unroll
            for (int np = 0; np < 2; np++)
#pragma unroll
                for (int mt = 0; mt < 2; mt++) {
                    mma_fp(acc[mt][np * 2 + 0], af[mt], bfr[np] + 0);
                    mma_fp(acc[mt][np * 2 + 1], af[mt], bfr[np] + 2);
                }
        }
        __syncthreads();
    }

    // ---- epilogue: store provisional + collect band entries ----
    const float* qnB = qn + (long)bz * SEQ * DIM;
    half* smT = reinterpret_cast<half*>(sm);
    half* Sb = S + (long)bz * SEQ * SEQ;
    bool mirror = (bx != by);

#pragma unroll
    for (int mt = 0; mt < 2; mt++) {
#pragma unroll
        for (int hf = 0; hf < 2; hf++) {
            int lr = wm * 32 + mt * 16 + (lane >> 2) + hf * 8;
            int gr = by * 128 + lr;
#pragma unroll
            for (int nt = 0; nt < 4; nt++) {
                float s0 = acc[mt][nt][hf * 2 + 0];
                float s1 = acc[mt][nt][hf * 2 + 1];
                int ln0 = wn * 32 + nt * 8 + (lane & 3) * 2;
                int gn0 = bx * 128 + ln0;
                if (fabsf(s0 - EPS_THR) < BAND) {
                    int p = atomicAdd(&rcount, 1);
                    if (p < RMAX) rlist[p] = (unsigned short)((lr << 8) | ln0);
                    else {
                        const float* qA = qnB + (long)gr * DIM;
                        const float* qB = qnB + (long)gn0 * DIM;
                        float a2 = 0.f;
#pragma unroll 8
                        for (int k = 0; k < DIM; k++) a2 = fmaf(qA[k], qB[k], a2);
                        s0 = a2;
                    }
                }
                if (fabsf(s1 - EPS_THR) < BAND) {
                    int p = atomicAdd(&rcount, 1);
                    if (p < RMAX) rlist[p] = (unsigned short)((lr << 8) | (ln0 + 1));
                    else {
                        const float* qA = qnB + (long)gr * DIM;
                        const float* qB = qnB + (long)(gn0 + 1) * DIM;
                        float a2 = 0.f;
#pragma unroll 8
                        for (int k = 0; k < DIM; k++) a2 = fmaf(qA[k], qB[k], a2);
                        s1 = a2;
                    }
                }
                s0 = (s0 > EPS_THR) ? s0 : 0.f;
                s1 = (s1 > EPS_THR) ? s1 : 0.f;
                half2 hh = __floats2half2_rn(s0, s1);
                *reinterpret_cast<half2*>(Sb + (long)gr * SEQ + gn0) = hh;
                if (mirror) {
                    smT[ln0 * TSTRIDE + lr]       = hh.x;
                    smT[(ln0 + 1) * TSTRIDE + lr] = hh.y;
                }
            }
        }
    }
    __syncthreads();

    // ---- warp-cooperative rescue fix-up (order-independent => deterministic)
    {
        int nr = rcount < RMAX ? rcount : RMAX;
        for (int i = wid; i < nr; i += 16) {
            int code = rlist[i];
            int lr = code >> 8, ln = code & 255;
            int gr = by * 128 + lr, gn = bx * 128 + ln;
            const float* qA = qnB + (long)gr * DIM;
            const float* qB = qnB + (long)gn * DIM;
            float part = 0.f;
            int k0 = lane * 16;
#pragma unroll
            for (int k = 0; k < 16; k++) part = fmaf(qA[k0 + k], qB[k0 + k], part);
#pragma unroll
            for (int o = 16; o > 0; o >>= 1) part += __shfl_down_sync(0xffffffffu, part, o);
            if (lane == 0) {
                float sx = (part > EPS_THR) ? part : 0.f;
                half h = __float2half_rn(sx);
                Sb[(long)gr * SEQ + gn] = h;
                if (mirror) smT[ln * TSTRIDE + lr] = h;
            }
        }
    }

    if (mirror) {
        __syncthreads();
        int r2 = tid >> 2;
        int q4 = tid & 3;
#pragma unroll
        for (int g = 0; g < 4; g++) {
            int j = q4 + g * 4;
            uint4 v = *reinterpret_cast<const uint4*>(smT + r2 * TSTRIDE + j * 8);
            *reinterpret_cast<uint4*>(Sb + (long)(bx * 128 + r2) * SEQ + by * 128 + j * 8) = v;
        }
    }
}

// ---------------------------------------------------------------------------
// fp16 1-pass mma GEMM, fp16 store: v = x * W_v^T (row-major out)
// ---------------------------------------------------------------------------
#define H_STAGE (2 * PART_B)
#define H_SMEM  (2 * H_STAGE)

__global__ __launch_bounds__(512, 1) void h_mma_kernel(
    const half* __restrict__ A, long ldA,
    const half* __restrict__ B, long ldB,
    int K, half* __restrict__ Oh, long ldO)
{
    extern __shared__ __align__(1024) char sm[];

    int tid = threadIdx.x;
    int wid = tid >> 5, lane = tid & 31;
    int wm = wid & 3, wn = wid >> 2;
    int bx = blockIdx.x, by = blockIdx.y;

    const half* At = A + (long)by * 128 * ldA;
    const half* Bt = B + (long)bx * 128 * ldB;

    uint32_t smb = smem_u32(sm);
    int NC = K / KC;

    auto issue_chunk = [&](int c) {
        uint32_t st = smb + (uint32_t)(c & 1) * H_STAGE;
        int k0 = c * KC;
        const half* srcs[2] = { At, Bt };
        long lds[2] = { ldA, ldB };
#pragma unroll
        for (int p = 0; p < 2; p++) {
#pragma unroll
            for (int i = 0; i < 2; i++) {
                int idx = tid + i * 512;
                int r = idx >> 3, c8 = idx & 7;
                uint32_t dst = st + (uint32_t)p * PART_B + (uint32_t)r * 128 + SWZC(c8 * 16, r);
                cp16(dst, srcs[p] + (long)r * lds[p] + k0 + c8 * 8);
            }
        }
        CP_COMMIT();
    };

    float acc[2][4][4];
#pragma unroll
    for (int mt = 0; mt < 2; mt++)
#pragma unroll
        for (int nt = 0; nt < 4; nt++)
#pragma unroll
            for (int i = 0; i < 4; i++) acc[mt][nt][i] = 0.0f;

    issue_chunk(0);

    for (int c = 0; c < NC; c++) {
        if (c + 1 < NC) { issue_chunk(c + 1); CP_WAIT(1); }
        else            { CP_WAIT(0); }
        __syncthreads();

        uint32_t base = smb + (uint32_t)(c & 1) * H_STAGE;
        uint32_t pA = base, pB = base + PART_B;

#pragma unroll
        for (int ks = 0; ks < 4; ks++) {
            uint32_t af[2][4], bfr[2][4];
#pragma unroll
            for (int mt = 0; mt < 2; mt++) {
                int arow = wm * 32 + mt * 16 + (lane & 15);
                uint32_t off = (uint32_t)arow * 128 + SWZC(ks * 32 + (lane >> 4) * 16, arow);
                LDSM4(af[mt][0], af[mt][1], af[mt][2], af[mt][3], pA + off);
            }
#pragma unroll
            for (int np = 0; np < 2; np++) {
                int brow = wn * 32 + np * 16 + (lane & 7) + ((lane >> 4) << 3);
                uint32_t off = (uint32_t)brow * 128 +
                               SWZC(ks * 32 + ((lane >> 3) & 1) * 16, brow);
                LDSM4(bfr[np][0], bfr[np][1], bfr[np][2], bfr[np][3], pB + off);
            }
#pragma unroll
            for (int np = 0; np < 2; np++)
#pragma unroll
                for (int mt = 0; mt < 2; mt++) {
                    mma_fp(acc[mt][np * 2 + 0], af[mt], bfr[np] + 0);
                    mma_fp(acc[mt][np * 2 + 1], af[mt], bfr[np] + 2);
                }
        }
        __syncthreads();
    }

#pragma unroll
    for (int mt = 0; mt < 2; mt++) {
#pragma unroll
        for (int hf = 0; hf < 2; hf++) {
            int gr = by * 128 + wm * 32 + mt * 16 + (lane >> 2) + hf * 8;
#pragma unroll
            for (int nt = 0; nt < 4; nt++) {
                int gn0 = bx * 128 + wn * 32 + nt * 8 + (lane & 3) * 2;
                half2 h = __floats2half2_rn(acc[mt][nt][hf * 2 + 0],
                                            acc[mt][nt][hf * 2 + 1]);
                *reinterpret_cast<half2*>(Oh + (long)gr * ldO + gn0) = h;
            }
        }
    }
}

// ---------------------------------------------------------------------------
// Sparse A*V + fused LayerNorm. Unroll-4 drain for 4x gather MLP.
// ---------------------------------------------------------------------------
__global__ __launch_bounds__(128) void av_ln_kernel(
    const half* __restrict__ S, const half* __restrict__ V,
    const float* __restrict__ gamma, const float* __restrict__ beta,
    float* __restrict__ out)
{
    int gr = blockIdx.x;
    int bz = gr >> 12;
    int n  = gr & (SEQ - 1);
    const half* Srow = S + ((long)bz * SEQ + n) * SEQ;
    const half* Vb   = V + (long)bz * SEQ * DIM;
    int tid = threadIdx.x, lane = tid & 31, wrp = tid >> 5;

    __shared__ int   s_idx[1024];
    __shared__ float s_val[1024];
    __shared__ int   s_wbase[4];

    float a0 = 0.f, a1 = 0.f, a2 = 0.f, a3 = 0.f;

#pragma unroll 1
    for (int ch = 0; ch < SEQ / 1024; ch++) {
        uint4 w = *reinterpret_cast<const uint4*>(Srow + ch * 1024 + tid * 8);
        uint32_t ws[4] = { w.x, w.y, w.z, w.w };
        uint16_t hs[8];
#pragma unroll
        for (int k = 0; k < 4; k++) {
            hs[2 * k]     = (uint16_t)(ws[k] & 0xFFFFu);
            hs[2 * k + 1] = (uint16_t)(ws[k] >> 16);
        }
        int nz = 0;
#pragma unroll
        for (int k = 0; k < 8; k++) nz += (hs[k] != 0);

        int inc = nz;
#pragma unroll
        for (int o = 1; o < 32; o <<= 1) {
            int vsh = __shfl_up_sync(0xffffffffu, inc, o);
            if (lane >= o) inc += vsh;
        }
        if (lane == 31) s_wbase[wrp] = inc;
        __syncthreads();
        int wb = 0;
#pragma unroll
        for (int ww = 0; ww < 4; ww++) if (ww < wrp) wb += s_wbase[ww];
        int total = s_wbase[0] + s_wbase[1] + s_wbase[2] + s_wbase[3];
        int pos = wb + inc - nz;
#pragma unroll
        for (int k = 0; k < 8; k++) {
            if (hs[k] != 0) {
                __half_raw hr; hr.x = hs[k];
                s_idx[pos] = ch * 1024 + tid * 8 + k;
                s_val[pos] = __half2float((half)hr);
                pos++;
            }
        }
        __syncthreads();

        // drain with 4-way MLP
        int i = 0;
        for (; i + 4 <= total; i += 4) {
            float sv0 = s_val[i],     sv1 = s_val[i + 1];
            float sv2 = s_val[i + 2], sv3 = s_val[i + 3];
            int m0 = s_idx[i],     m1 = s_idx[i + 1];
            int m2 = s_idx[i + 2], m3 = s_idx[i + 3];
            uint2 v0 = *reinterpret_cast<const uint2*>(Vb + (long)m0 * DIM + tid * 4);
            uint2 v1 = *reinterpret_cast<const uint2*>(Vb + (long)m1 * DIM + tid * 4);
            uint2 v2 = *reinterpret_cast<const uint2*>(Vb + (long)m2 * DIM + tid * 4);
            uint2 v3 = *reinterpret_cast<const uint2*>(Vb + (long)m3 * DIM + tid * 4);
#define ACC4(vv, sv) do {                                           \
                half2 _h0 = *reinterpret_cast<half2*>(&(vv).x);     \
                half2 _h1 = *reinterpret_cast<half2*>(&(vv).y);     \
                float2 _f0 = __half22float2(_h0);                   \
                float2 _f1 = __half22float2(_h1);                   \
                a0 = fmaf((sv), _f0.x, a0);                         \
                a1 = fmaf((sv), _f0.y, a1);                         \
                a2 = fmaf((sv), _f1.x, a2);                         \
                a3 = fmaf((sv), _f1.y, a3);                         \
            } while (0)
            ACC4(v0, sv0); ACC4(v1, sv1); ACC4(v2, sv2); ACC4(v3, sv3);
        }
        for (; i < total; i++) {
            float sv = s_val[i];
            int m = s_idx[i];
            uint2 vv = *reinterpret_cast<const uint2*>(Vb + (long)m * DIM + tid * 4);
            ACC4(vv, sv);
        }
#undef ACC4
        __syncthreads();
    }

    // fused LayerNorm over 512 values (4 per thread)
    float s1 = a0 + a1 + a2 + a3;
    float s2 = a0 * a0 + a1 * a1 + a2 * a2 + a3 * a3;
    float ts1 = block_reduce_sum_128(s1);
    float ts2 = block_reduce_sum_128(s2);
    float mean = ts1 * (1.0f / DIM);
    float var  = ts2 * (1.0f / DIM) - mean * mean;
    float inv = rsqrtf(var + LN_EPS);

    float4 g = *reinterpret_cast<const float4*>(gamma + tid * 4);
    float4 b = *reinterpret_cast<const float4*>(beta + tid * 4);
    float4 o;
    o.x = (a0 - mean) * inv * g.x + b.x;
    o.y = (a1 - mean) * inv * g.y + b.y;
    o.z = (a2 - mean) * inv * g.z + b.z;
    o.w = (a3 - mean) * inv * g.w + b.w;
    *reinterpret_cast<float4*>(out + (long)gr * DIM + tid * 4) = o;
}

// ---------------------------------------------------------------------------
// Launch
// ---------------------------------------------------------------------------
extern "C" void kernel_launch(void* const* d_in, const int* in_sizes, int n_in,
                              void* d_out, int out_size)
{
    const float* x     = (const float*)d_in[0];
    const float* W_qk  = (const float*)d_in[1];
    const float* W_v   = (const float*)d_in[2];
    const float* gamma = (const float*)d_in[3];
    const float* beta  = (const float*)d_in[4];
    float* out = (float*)d_out;

    float* qp;
    half *qn16, *x16, *w16, *v16, *s16;
    cudaGetSymbolAddress((void**)&qp,   g_q);
    cudaGetSymbolAddress((void**)&qn16, g_qn16);
    cudaGetSymbolAddress((void**)&x16,  g_x16);
    cudaGetSymbolAddress((void**)&w16,  g_w16);
    cudaGetSymbolAddress((void**)&v16,  g_v16);
    cudaGetSymbolAddress((void**)&s16,  g_s16);

    cudaFuncSetAttribute((const void*)s_mma_kernel, cudaFuncAttributeMaxDynamicSharedMemorySize, S1_SMEM);
    cudaFuncSetAttribute((const void*)h_mma_kernel, cudaFuncAttributeMaxDynamicSharedMemorySize, H_SMEM);

    // 1) q projection in fp32 (mask-critical; MUST stay fp32-exact)
    {
        dim3 grid(DIM / BN, ROWS / BM, 1);
        gemm_abt_kernel<<<grid, 256>>>(x, W_qk, qp, ROWS, DIM, DIM);
    }

    // 2) fp16 conversions for the V path
    f2h_kernel<<<((long)ROWS * DIM / 4 + 255) / 256, 256>>>(x, x16, (long)ROWS * DIM);
    f2h_kernel<<<((long)DIM * DIM / 4 + 255) / 256, 256>>>(W_v, w16, (long)DIM * DIM);

    // 3) v = x * W_v^T (fp16 1-pass; row-major [ROWS, DIM])
    {
        dim3 grid(DIM / 128, ROWS / 128, 1);
        h_mma_kernel<<<grid, 512, H_SMEM>>>(x16, DIM, w16, DIM, DIM, v16, DIM);
    }

    // 4) L2-normalize q rows + fp16 plane
    l2norm_kernel<<<ROWS, 128>>>(qp, qn16);

    // 5) S = Qn*Qn^T — 1-pass fp16, triangular + mirror, cooperative rescue
    {
        int nt = SEQ / 128;
        dim3 grid(nt * (nt + 1) / 2, 1, BATCH);
        s_mma_kernel<<<grid, 512, S1_SMEM>>>(qn16, qp, s16);
    }

    // 6) out = LayerNorm(S * V) — sparse gather, fused LN
    av_ln_kernel<<<ROWS, 128>>>(s16, v16, gamma, beta, out);
}

// round 10
// speedup vs baseline: 7.0503x; 1.4053x over previous
#include <cuda_runtime.h>
#include <cuda_fp16.h>
#include <cstdint>
#include <math.h>

// ---------------------------------------------------------------------------
// Problem constants
// ---------------------------------------------------------------------------
#define BATCH 4
#define SEQ   4096
#define DIM   512
#define ROWS  (BATCH * SEQ)          // 16384
#define EPS_THR 0.1f
#define BAND    4e-4f
#define LN_EPS  1e-5f
#define NORM_EPS 1e-12f
#define LO_SCALE 2048.0f             // 2^11
#define LO_INV   (1.0f / 2048.0f)

// ---------------------------------------------------------------------------
// Scratch (__device__ globals; no runtime allocation)
// ---------------------------------------------------------------------------
__device__ float g_q   [(size_t)ROWS * DIM];          // fp32 q / qn
__device__ half  g_qn16[(size_t)ROWS * DIM];          // qn fp16
__device__ half  g_x16 [(size_t)ROWS * DIM];          // x fp16 hi (v path + q hi)
__device__ half  g_xlo [(size_t)ROWS * DIM];          // x fp16 lo * 2^11
__device__ half  g_w16 [(size_t)DIM * DIM];           // W_v fp16
__device__ half  g_whi [(size_t)DIM * DIM];           // W_qk fp16 hi
__device__ half  g_wlo [(size_t)DIM * DIM];           // W_qk fp16 lo * 2^11
__device__ half  g_v16 [(size_t)ROWS * DIM];          // v fp16 row-major
__device__ half  g_s16 [(size_t)BATCH * SEQ * SEQ];   // masked attn fp16

// ---------------------------------------------------------------------------
// PTX helpers (arch-agnostic: sm_80+)
// ---------------------------------------------------------------------------
__device__ __forceinline__ uint32_t smem_u32(const void* p) {
    uint32_t a;
    asm("{ .reg .u64 t; cvta.to.shared.u64 t, %1; cvt.u32.u64 %0, t; }"
        : "=r"(a) : "l"(p));
    return a;
}

__device__ __forceinline__ void cp16(uint32_t dst, const void* src) {
    asm volatile("cp.async.cg.shared.global [%0], [%1], 16;" :: "r"(dst), "l"(src));
}
#define CP_COMMIT() asm volatile("cp.async.commit_group;" ::: "memory")
#define CP_WAIT(n)  asm volatile("cp.async.wait_group %0;" :: "n"(n) : "memory")

#define LDSM4(r0, r1, r2, r3, addr) \
    asm volatile("ldmatrix.sync.aligned.m8n8.x4.shared.b16 {%0,%1,%2,%3},[%4];" \
                 : "=r"(r0), "=r"(r1), "=r"(r2), "=r"(r3) : "r"(addr))

__device__ __forceinline__ void mma_fp(float* c, const uint32_t* a, const uint32_t* b) {
    asm volatile(
        "mma.sync.aligned.m16n8k16.row.col.f32.f16.f16.f32 "
        "{%0,%1,%2,%3},{%4,%5,%6,%7},{%8,%9},{%0,%1,%2,%3};"
        : "+f"(c[0]), "+f"(c[1]), "+f"(c[2]), "+f"(c[3])
        : "r"(a[0]), "r"(a[1]), "r"(a[2]), "r"(a[3]), "r"(b[0]), "r"(b[1]));
}

#define SWZC(c, r) ((uint32_t)(c) ^ ((((uint32_t)(r)) & 7u) << 4))

#define KC      64
#define PART_B  16384                  // 128 rows x 128 bytes
#define TSTRIDE 136

// ---------------------------------------------------------------------------
// Split kernels: fp32 -> fp16 hi + scaled lo
// ---------------------------------------------------------------------------
__global__ __launch_bounds__(256) void split_x_kernel(
    const float* __restrict__ src, half* __restrict__ dhi, half* __restrict__ dlo, long n)
{
    long i = ((long)blockIdx.x * 256 + threadIdx.x) * 4;
    if (i < n) {
        float4 f = *reinterpret_cast<const float4*>(src + i);
        float fv[4] = { f.x, f.y, f.z, f.w };
        half hi[4], lo[4];
#pragma unroll
        for (int k = 0; k < 4; k++) {
            hi[k] = __float2half_rn(fv[k]);
            lo[k] = __float2half_rn((fv[k] - __half2float(hi[k])) * LO_SCALE);
        }
        *reinterpret_cast<uint2*>(dhi + i) = *reinterpret_cast<uint2*>(hi);
        *reinterpret_cast<uint2*>(dlo + i) = *reinterpret_cast<uint2*>(lo);
    }
}

// W_qk -> fp16 hi + scaled lo ; W_v -> fp16
__global__ __launch_bounds__(256) void split_w_kernel(
    const float* __restrict__ wqk, const float* __restrict__ wv,
    half* __restrict__ whi, half* __restrict__ wlo, half* __restrict__ w16)
{
    long i = ((long)blockIdx.x * 256 + threadIdx.x) * 4;
    if (i < (long)DIM * DIM) {
        float4 f = *reinterpret_cast<const float4*>(wqk + i);
        float fv[4] = { f.x, f.y, f.z, f.w };
        half hi[4], lo[4];
#pragma unroll
        for (int k = 0; k < 4; k++) {
            hi[k] = __float2half_rn(fv[k]);
            lo[k] = __float2half_rn((fv[k] - __half2float(hi[k])) * LO_SCALE);
        }
        *reinterpret_cast<uint2*>(whi + i) = *reinterpret_cast<uint2*>(hi);
        *reinterpret_cast<uint2*>(wlo + i) = *reinterpret_cast<uint2*>(lo);

        float4 g = *reinterpret_cast<const float4*>(wv + i);
        half2 h0 = __floats2half2_rn(g.x, g.y);
        half2 h1 = __floats2half2_rn(g.z, g.w);
        uint2 u;
        u.x = *reinterpret_cast<uint32_t*>(&h0);
        u.y = *reinterpret_cast<uint32_t*>(&h1);
        *reinterpret_cast<uint2*>(w16 + i) = u;
    }
}

// ---------------------------------------------------------------------------
// Block reduce (128 threads)
// ---------------------------------------------------------------------------
__device__ __forceinline__ float block_reduce_sum_128(float v)
{
    __shared__ float sh[4];
#pragma unroll
    for (int o = 16; o > 0; o >>= 1) v += __shfl_down_sync(0xffffffffu, v, o);
    int lane = threadIdx.x & 31, w = threadIdx.x >> 5;
    if (lane == 0) sh[w] = v;
    __syncthreads();
    float total = sh[0] + sh[1] + sh[2] + sh[3];
    __syncthreads();
    return total;
}

// L2-normalize q rows in place; emit fp16 plane
__global__ __launch_bounds__(128) void l2norm_kernel(
    float* __restrict__ q, half* __restrict__ q16)
{
    long base = (long)blockIdx.x * DIM;
    float* p = q + base;
    float s = 0.0f;
#pragma unroll
    for (int i = threadIdx.x; i < DIM; i += 128) { float v = p[i]; s += v * v; }
    float total = block_reduce_sum_128(s);
    float inv = 1.0f / fmaxf(sqrtf(total), NORM_EPS);
#pragma unroll
    for (int i = threadIdx.x; i < DIM; i += 128) {
        float v = p[i] * inv;
        p[i] = v;
        q16[base + i] = __float2half_rn(v);
    }
}

// ---------------------------------------------------------------------------
// q projection: 3-pass fp16-split mma (fp32-equivalent), dual accumulators.
// q = (xhi + xlo/2^11) * (whi + wlo/2^11)^T, dropping lo*lo (2^-24 rel).
// acc0 <- xhi*whi ; acc1 <- xhi*wlo + xlo*whi ; q = acc0 + acc1 * 2^-11
// ---------------------------------------------------------------------------
#define Q_STAGE (4 * PART_B)          // 64KB: xhi xlo whi wlo
#define Q_SMEM  (2 * Q_STAGE)         // 128KB

__global__ __launch_bounds__(512, 1) void q_mma_kernel(
    const half* __restrict__ Ahi, const half* __restrict__ Alo,
    const half* __restrict__ Bhi, const half* __restrict__ Blo,
    float* __restrict__ C)
{
    extern __shared__ __align__(1024) char sm[];

    int tid = threadIdx.x;
    int wid = tid >> 5, lane = tid & 31;
    int wm = wid & 3, wn = wid >> 2;
    int bx = blockIdx.x, by = blockIdx.y;

    const half* Ah = Ahi + (long)by * 128 * DIM;
    const half* Al = Alo + (long)by * 128 * DIM;
    const half* Bh = Bhi + (long)bx * 128 * DIM;
    const half* Bl = Blo + (long)bx * 128 * DIM;

    uint32_t smb = smem_u32(sm);
    const int NC = DIM / KC;   // 8

    auto issue_chunk = [&](int c) {
        uint32_t st = smb + (uint32_t)(c & 1) * Q_STAGE;
        int k0 = c * KC;
        const half* srcs[4] = { Ah, Al, Bh, Bl };
#pragma unroll
        for (int p = 0; p < 4; p++) {
#pragma unroll
            for (int i = 0; i < 2; i++) {
                int idx = tid + i * 512;
                int r = idx >> 3, c8 = idx & 7;
                uint32_t dst = st + (uint32_t)p * PART_B + (uint32_t)r * 128 + SWZC(c8 * 16, r);
                cp16(dst, srcs[p] + (long)r * DIM + k0 + c8 * 8);
            }
        }
        CP_COMMIT();
    };

    float acc0[2][4][4], acc1[2][4][4];
#pragma unroll
    for (int mt = 0; mt < 2; mt++)
#pragma unroll
        for (int nt = 0; nt < 4; nt++)
#pragma unroll
            for (int i = 0; i < 4; i++) { acc0[mt][nt][i] = 0.0f; acc1[mt][nt][i] = 0.0f; }

    issue_chunk(0);

    for (int c = 0; c < NC; c++) {
        if (c + 1 < NC) { issue_chunk(c + 1); CP_WAIT(1); }
        else            { CP_WAIT(0); }
        __syncthreads();

        uint32_t base = smb + (uint32_t)(c & 1) * Q_STAGE;
        uint32_t pAh = base, pAl = base + PART_B, pBh = base + 2 * PART_B, pBl = base + 3 * PART_B;

#pragma unroll
        for (int ks = 0; ks < 4; ks++) {
            uint32_t ah[2][4], al[2][4], bh[2][4], bl[2][4];
#pragma unroll
            for (int mt = 0; mt < 2; mt++) {
                int arow = wm * 32 + mt * 16 + (lane & 15);
                uint32_t off = (uint32_t)arow * 128 + SWZC(ks * 32 + (lane >> 4) * 16, arow);
                LDSM4(ah[mt][0], ah[mt][1], ah[mt][2], ah[mt][3], pAh + off);
                LDSM4(al[mt][0], al[mt][1], al[mt][2], al[mt][3], pAl + off);
            }
#pragma unroll
            for (int np = 0; np < 2; np++) {
                int brow = wn * 32 + np * 16 + (lane & 7) + ((lane >> 4) << 3);
                uint32_t off = (uint32_t)brow * 128 +
                               SWZC(ks * 32 + ((lane >> 3) & 1) * 16, brow);
                LDSM4(bh[np][0], bh[np][1], bh[np][2], bh[np][3], pBh + off);
                LDSM4(bl[np][0], bl[np][1], bl[np][2], bl[np][3], pBl + off);
            }
            // pass 1: hi*hi -> acc0
#pragma unroll
            for (int np = 0; np < 2; np++)
#pragma unroll
                for (int mt = 0; mt < 2; mt++) {
                    mma_fp(acc0[mt][np * 2 + 0], ah[mt], bh[np] + 0);
                    mma_fp(acc0[mt][np * 2 + 1], ah[mt], bh[np] + 2);
                }
            // pass 2: hi*lo -> acc1
#pragma unroll
            for (int np = 0; np < 2; np++)
#pragma unroll
                for (int mt = 0; mt < 2; mt++) {
                    mma_fp(acc1[mt][np * 2 + 0], ah[mt], bl[np] + 0);
                    mma_fp(acc1[mt][np * 2 + 1], ah[mt], bl[np] + 2);
                }
            // pass 3: lo*hi -> acc1
#pragma unroll
            for (int np = 0; np < 2; np++)
#pragma unroll
                for (int mt = 0; mt < 2; mt++) {
                    mma_fp(acc1[mt][np * 2 + 0], al[mt], bh[np] + 0);
                    mma_fp(acc1[mt][np * 2 + 1], al[mt], bh[np] + 2);
                }
        }
        __syncthreads();
    }

#pragma unroll
    for (int mt = 0; mt < 2; mt++) {
#pragma unroll
        for (int hf = 0; hf < 2; hf++) {
            int gr = by * 128 + wm * 32 + mt * 16 + (lane >> 2) + hf * 8;
#pragma unroll
            for (int nt = 0; nt < 4; nt++) {
                int gn0 = bx * 128 + wn * 32 + nt * 8 + (lane & 3) * 2;
                float2 f2;
                f2.x = acc0[mt][nt][hf * 2 + 0] + acc1[mt][nt][hf * 2 + 0] * LO_INV;
                f2.y = acc0[mt][nt][hf * 2 + 1] + acc1[mt][nt][hf * 2 + 1] * LO_INV;
                *reinterpret_cast<float2*>(C + (long)gr * DIM + gn0) = f2;
            }
        }
    }
}

// ---------------------------------------------------------------------------
// S kernel: 1-pass fp16 mma; triangular + mirror; cooperative rescue.
// ---------------------------------------------------------------------------
#define S1_STAGE (2 * PART_B)
#define S1_SMEM  (2 * S1_STAGE)
#define RMAX 512

__global__ __launch_bounds__(512, 1) void s_mma_kernel(
    const half* __restrict__ qn16, const float* __restrict__ qn,
    half* __restrict__ S)
{
    extern __shared__ __align__(1024) char sm[];
    __shared__ int rcount;
    __shared__ unsigned short rlist[RMAX];

    int tid = threadIdx.x;
    int wid = tid >> 5, lane = tid & 31;
    int wm = wid & 3, wn = wid >> 2;
    int bz = blockIdx.z;

    int t = blockIdx.x;
    int bi = (int)((sqrtf(8.0f * (float)t + 1.0f) - 1.0f) * 0.5f);
    while ((bi + 1) * (bi + 2) / 2 <= t) ++bi;
    while (bi * (bi + 1) / 2 > t) --bi;
    int by = t - bi * (bi + 1) / 2;
    int bx = bi;

    const half* At = qn16 + (long)bz * SEQ * DIM + (long)by * 128 * DIM;
    const half* Bt = qn16 + (long)bz * SEQ * DIM + (long)bx * 128 * DIM;

    uint32_t smb = smem_u32(sm);
    const int NC = DIM / KC;

    auto issue_chunk = [&](int c) {
        uint32_t st = smb + (uint32_t)(c & 1) * S1_STAGE;
        int k0 = c * KC;
        const half* srcs[2] = { At, Bt };
#pragma unroll
        for (int p = 0; p < 2; p++) {
#pragma unroll
            for (int i = 0; i < 2; i++) {
                int idx = tid + i * 512;
                int r = idx >> 3, c8 = idx & 7;
                uint32_t dst = st + (uint32_t)p * PART_B + (uint32_t)r * 128 + SWZC(c8 * 16, r);
                cp16(dst, srcs[p] + (long)r * DIM + k0 + c8 * 8);
            }
        }
        CP_COMMIT();
    };

    if (tid == 0) rcount = 0;

    float acc[2][4][4];
#pragma unroll
    for (int mt = 0; mt < 2; mt++)
#pragma unroll
        for (int nt = 0; nt < 4; nt++)
#pragma unroll
            for (int i = 0; i < 4; i++) acc[mt][nt][i] = 0.0f;

    issue_chunk(0);

    for (int c = 0; c < NC; c++) {
        if (c + 1 < NC) { issue_chunk(c + 1); CP_WAIT(1); }
        else            { CP_WAIT(0); }
        __syncthreads();

        uint32_t base = smb + (uint32_t)(c & 1) * S1_STAGE;
        uint32_t pA = base, pB = base + PART_B;

#pragma unroll
        for (int ks = 0; ks < 4; ks++) {
            uint32_t af[2][4], bfr[2][4];
#pragma unroll
            for (int mt = 0; mt < 2; mt++) {
                int arow = wm * 32 + mt * 16 + (lane & 15);
                uint32_t off = (uint32_t)arow * 128 + SWZC(ks * 32 + (lane >> 4) * 16, arow);
                LDSM4(af[mt][0], af[mt][1], af[mt][2], af[mt][3], pA + off);
            }
#pragma unroll
            for (int np = 0; np < 2; np++) {
                int brow = wn * 32 + np * 16 + (lane & 7) + ((lane >> 4) << 3);
                uint32_t off = (uint32_t)brow * 128 +
                               SWZC(ks * 32 + ((lane >> 3) & 1) * 16, brow);
                LDSM4(bfr[np][0], bfr[np][1], bfr[np][2], bfr[np][3], pB + off);
            }
#pragma unroll
            for (int np = 0; np < 2; np++)
#pragma unroll
                for (int mt = 0; mt < 2; mt++) {
                    mma_fp(acc[mt][np * 2 + 0], af[mt], bfr[np] + 0);
                    mma_fp(acc[mt][np * 2 + 1], af[mt], bfr[np] + 2);
                }
        }
        __syncthreads();
    }

    // ---- epilogue: store provisional + collect band entries ----
    const float* qnB = qn + (long)bz * SEQ * DIM;
    half* smT = reinterpret_cast<half*>(sm);
    half* Sb = S + (long)bz * SEQ * SEQ;
    bool mirror = (bx != by);

#pragma unroll
    for (int mt = 0; mt < 2; mt++) {
#pragma unroll
        for (int hf = 0; hf < 2; hf++) {
            int lr = wm * 32 + mt * 16 + (lane >> 2) + hf * 8;
            int gr = by * 128 + lr;
#pragma unroll
            for (int nt = 0; nt < 4; nt++) {
                float s0 = acc[mt][nt][hf * 2 + 0];
                float s1 = acc[mt][nt][hf * 2 + 1];
                int ln0 = wn * 32 + nt * 8 + (lane & 3) * 2;
                int gn0 = bx * 128 + ln0;
                if (fabsf(s0 - EPS_THR) < BAND) {
                    int p = atomicAdd(&rcount, 1);
                    if (p < RMAX) rlist[p] = (unsigned short)((lr << 8) | ln0);
                    else {
                        const float* qA = qnB + (long)gr * DIM;
                        const float* qB = qnB + (long)gn0 * DIM;
                        float a2 = 0.f;
#pragma unroll 8
                        for (int k = 0; k < DIM; k++) a2 = fmaf(qA[k], qB[k], a2);
                        s0 = a2;
                    }
                }
                if (fabsf(s1 - EPS_THR) < BAND) {
                    int p = atomicAdd(&rcount, 1);
                    if (p < RMAX) rlist[p] = (unsigned short)((lr << 8) | (ln0 + 1));
                    else {
                        const float* qA = qnB + (long)gr * DIM;
                        const float* qB = qnB + (long)(gn0 + 1) * DIM;
                        float a2 = 0.f;
#pragma unroll 8
                        for (int k = 0; k < DIM; k++) a2 = fmaf(qA[k], qB[k], a2);
                        s1 = a2;
                    }
                }
                s0 = (s0 > EPS_THR) ? s0 : 0.f;
                s1 = (s1 > EPS_THR) ? s1 : 0.f;
                half2 hh = __floats2half2_rn(s0, s1);
                *reinterpret_cast<half2*>(Sb + (long)gr * SEQ + gn0) = hh;
                if (mirror) {
                    smT[ln0 * TSTRIDE + lr]       = hh.x;
                    smT[(ln0 + 1) * TSTRIDE + lr] = hh.y;
                }
            }
        }
    }
    __syncthreads();

    // ---- warp-cooperative rescue fix-up ----
    {
        int nr = rcount < RMAX ? rcount : RMAX;
        for (int i = wid; i < nr; i += 16) {
            int code = rlist[i];
            int lr = code >> 8, ln = code & 255;
            int gr = by * 128 + lr, gn = bx * 128 + ln;
            const float* qA = qnB + (long)gr * DIM;
            const float* qB = qnB + (long)gn * DIM;
            float part = 0.f;
            int k0 = lane * 16;
#pragma unroll
            for (int k = 0; k < 16; k++) part = fmaf(qA[k0 + k], qB[k0 + k], part);
#pragma unroll
            for (int o = 16; o > 0; o >>= 1) part += __shfl_down_sync(0xffffffffu, part, o);
            if (lane == 0) {
                float sx = (part > EPS_THR) ? part : 0.f;
                half h = __float2half_rn(sx);
                Sb[(long)gr * SEQ + gn] = h;
                if (mirror) smT[ln * TSTRIDE + lr] = h;
            }
        }
    }

    if (mirror) {
        __syncthreads();
        int r2 = tid >> 2;
        int q4 = tid & 3;
#pragma unroll
        for (int g = 0; g < 4; g++) {
            int j = q4 + g * 4;
            uint4 v = *reinterpret_cast<const uint4*>(smT + r2 * TSTRIDE + j * 8);
            *reinterpret_cast<uint4*>(Sb + (long)(bx * 128 + r2) * SEQ + by * 128 + j * 8) = v;
        }
    }
}

// ---------------------------------------------------------------------------
// fp16 1-pass mma GEMM, fp16 store: v = x * W_v^T (row-major out)
// ---------------------------------------------------------------------------
#define H_STAGE (2 * PART_B)
#define H_SMEM  (2 * H_STAGE)

__global__ __launch_bounds__(512, 1) void h_mma_kernel(
    const half* __restrict__ A, long ldA,
    const half* __restrict__ B, long ldB,
    int K, half* __restrict__ Oh, long ldO)
{
    extern __shared__ __align__(1024) char sm[];

    int tid = threadIdx.x;
    int wid = tid >> 5, lane = tid & 31;
    int wm = wid & 3, wn = wid >> 2;
    int bx = blockIdx.x, by = blockIdx.y;

    const half* At = A + (long)by * 128 * ldA;
    const half* Bt = B + (long)bx * 128 * ldB;

    uint32_t smb = smem_u32(sm);
    int NC = K / KC;

    auto issue_chunk = [&](int c) {
        uint32_t st = smb + (uint32_t)(c & 1) * H_STAGE;
        int k0 = c * KC;
        const half* srcs[2] = { At, Bt };
        long lds[2] = { ldA, ldB };
#pragma unroll
        for (int p = 0; p < 2; p++) {
#pragma unroll
            for (int i = 0; i < 2; i++) {
                int idx = tid + i * 512;
                int r = idx >> 3, c8 = idx & 7;
                uint32_t dst = st + (uint32_t)p * PART_B + (uint32_t)r * 128 + SWZC(c8 * 16, r);
                cp16(dst, srcs[p] + (long)r * lds[p] + k0 + c8 * 8);
            }
        }
        CP_COMMIT();
    };

    float acc[2][4][4];
#pragma unroll
    for (int mt = 0; mt < 2; mt++)
#pragma unroll
        for (int nt = 0; nt < 4; nt++)
#pragma unroll
            for (int i = 0; i < 4; i++) acc[mt][nt][i] = 0.0f;

    issue_chunk(0);

    for (int c = 0; c < NC; c++) {
        if (c + 1 < NC) { issue_chunk(c + 1); CP_WAIT(1); }
        else            { CP_WAIT(0); }
        __syncthreads();

        uint32_t base = smb + (uint32_t)(c & 1) * H_STAGE;
        uint32_t pA = base, pB = base + PART_B;

#pragma unroll
        for (int ks = 0; ks < 4; ks++) {
            uint32_t af[2][4], bfr[2][4];
#pragma unroll
            for (int mt = 0; mt < 2; mt++) {
                int arow = wm * 32 + mt * 16 + (lane & 15);
                uint32_t off = (uint32_t)arow * 128 + SWZC(ks * 32 + (lane >> 4) * 16, arow);
                LDSM4(af[mt][0], af[mt][1], af[mt][2], af[mt][3], pA + off);
            }
#pragma unroll
            for (int np = 0; np < 2; np++) {
                int brow = wn * 32 + np * 16 + (lane & 7) + ((lane >> 4) << 3);
                uint32_t off = (uint32_t)brow * 128 +
                               SWZC(ks * 32 + ((lane >> 3) & 1) * 16, brow);
                LDSM4(bfr[np][0], bfr[np][1], bfr[np][2], bfr[np][3], pB + off);
            }
#pragma unroll
            for (int np = 0; np < 2; np++)
#pragma unroll
                for (int mt = 0; mt < 2; mt++) {
                    mma_fp(acc[mt][np * 2 + 0], af[mt], bfr[np] + 0);
                    mma_fp(acc[mt][np * 2 + 1], af[mt], bfr[np] + 2);
                }
        }
        __syncthreads();
    }

#pragma unroll
    for (int mt = 0; mt < 2; mt++) {
#pragma unroll
        for (int hf = 0; hf < 2; hf++) {
            int gr = by * 128 + wm * 32 + mt * 16 + (lane >> 2) + hf * 8;
#pragma unroll
            for (int nt = 0; nt < 4; nt++) {
                int gn0 = bx * 128 + wn * 32 + nt * 8 + (lane & 3) * 2;
                half2 h = __floats2half2_rn(acc[mt][nt][hf * 2 + 0],
                                            acc[mt][nt][hf * 2 + 1]);
                *reinterpret_cast<half2*>(Oh + (long)gr * ldO + gn0) = h;
            }
        }
    }
}

// ---------------------------------------------------------------------------
// Sparse A*V + fused LayerNorm. Unroll-4 drain.
// ---------------------------------------------------------------------------
__global__ __launch_bounds__(128) void av_ln_kernel(
    const half* __restrict__ S, const half* __restrict__ V,
    const float* __restrict__ gamma, const float* __restrict__ beta,
    float* __restrict__ out)
{
    int gr = blockIdx.x;
    int bz = gr >> 12;
    int n  = gr & (SEQ - 1);
    const half* Srow = S + ((long)bz * SEQ + n) * SEQ;
    const half* Vb   = V + (long)bz * SEQ * DIM;
    int tid = threadIdx.x, lane = tid & 31, wrp = tid >> 5;

    __shared__ int   s_idx[1024];
    __shared__ float s_val[1024];
    __shared__ int   s_wbase[4];

    float a0 = 0.f, a1 = 0.f, a2 = 0.f, a3 = 0.f;

#pragma unroll 1
    for (int ch = 0; ch < SEQ / 1024; ch++) {
        uint4 w = *reinterpret_cast<const uint4*>(Srow + ch * 1024 + tid * 8);
        uint32_t ws[4] = { w.x, w.y, w.z, w.w };
        uint16_t hs[8];
#pragma unroll
        for (int k = 0; k < 4; k++) {
            hs[2 * k]     = (uint16_t)(ws[k] & 0xFFFFu);
            hs[2 * k + 1] = (uint16_t)(ws[k] >> 16);
        }
        int nz = 0;
#pragma unroll
        for (int k = 0; k < 8; k++) nz += (hs[k] != 0);

        int inc = nz;
#pragma unroll
        for (int o = 1; o < 32; o <<= 1) {
            int vsh = __shfl_up_sync(0xffffffffu, inc, o);
            if (lane >= o) inc += vsh;
        }
        if (lane == 31) s_wbase[wrp] = inc;
        __syncthreads();
        int wb = 0;
#pragma unroll
        for (int ww = 0; ww < 4; ww++) if (ww < wrp) wb += s_wbase[ww];
        int total = s_wbase[0] + s_wbase[1] + s_wbase[2] + s_wbase[3];
        int pos = wb + inc - nz;
#pragma unroll
        for (int k = 0; k < 8; k++) {
            if (hs[k] != 0) {
                __half_raw hr; hr.x = hs[k];
                s_idx[pos] = ch * 1024 + tid * 8 + k;
                s_val[pos] = __half2float((half)hr);
                pos++;
            }
        }
        __syncthreads();

        int i = 0;
        for (; i + 4 <= total; i += 4) {
            float sv0 = s_val[i],     sv1 = s_val[i + 1];
            float sv2 = s_val[i + 2], sv3 = s_val[i + 3];
            int m0 = s_idx[i],     m1 = s_idx[i + 1];
            int m2 = s_idx[i + 2], m3 = s_idx[i + 3];
            uint2 v0 = *reinterpret_cast<const uint2*>(Vb + (long)m0 * DIM + tid * 4);
            uint2 v1 = *reinterpret_cast<const uint2*>(Vb + (long)m1 * DIM + tid * 4);
            uint2 v2 = *reinterpret_cast<const uint2*>(Vb + (long)m2 * DIM + tid * 4);
            uint2 v3 = *reinterpret_cast<const uint2*>(Vb + (long)m3 * DIM + tid * 4);
#define ACC4(vv, sv) do {                                           \
                half2 _h0 = *reinterpret_cast<half2*>(&(vv).x);     \
                half2 _h1 = *reinterpret_cast<half2*>(&(vv).y);     \
                float2 _f0 = __half22float2(_h0);                   \
                float2 _f1 = __half22float2(_h1);                   \
                a0 = fmaf((sv), _f0.x, a0);                         \
                a1 = fmaf((sv), _f0.y, a1);                         \
                a2 = fmaf((sv), _f1.x, a2);                         \
                a3 = fmaf((sv), _f1.y, a3);                         \
            } while (0)
            ACC4(v0, sv0); ACC4(v1, sv1); ACC4(v2, sv2); ACC4(v3, sv3);
        }
        for (; i < total; i++) {
            float sv = s_val[i];
            int m = s_idx[i];
            uint2 vv = *reinterpret_cast<const uint2*>(Vb + (long)m * DIM + tid * 4);
            ACC4(vv, sv);
        }
#undef ACC4
        __syncthreads();
    }

    float s1 = a0 + a1 + a2 + a3;
    float s2 = a0 * a0 + a1 * a1 + a2 * a2 + a3 * a3;
    float ts1 = block_reduce_sum_128(s1);
    float ts2 = block_reduce_sum_128(s2);
    float mean = ts1 * (1.0f / DIM);
    float var  = ts2 * (1.0f / DIM) - mean * mean;
    float inv = rsqrtf(var + LN_EPS);

    float4 g = *reinterpret_cast<const float4*>(gamma + tid * 4);
    float4 b = *reinterpret_cast<const float4*>(beta + tid * 4);
    float4 o;
    o.x = (a0 - mean) * inv * g.x + b.x;
    o.y = (a1 - mean) * inv * g.y + b.y;
    o.z = (a2 - mean) * inv * g.z + b.z;
    o.w = (a3 - mean) * inv * g.w + b.w;
    *reinterpret_cast<float4*>(out + (long)gr * DIM + tid * 4) = o;
}

// ---------------------------------------------------------------------------
// Launch
// ---------------------------------------------------------------------------
extern "C" void kernel_launch(void* const* d_in, const int* in_sizes, int n_in,
                              void* d_out, int out_size)
{
    const float* x     = (const float*)d_in[0];
    const float* W_qk  = (const float*)d_in[1];
    const float* W_v   = (const float*)d_in[2];
    const float* gamma = (const float*)d_in[3];
    const float* beta  = (const float*)d_in[4];
    float* out = (float*)d_out;

    float* qp;
    half *qn16, *x16, *xlo, *w16, *whi, *wlo, *v16, *s16;
    cudaGetSymbolAddress((void**)&qp,   g_q);
    cudaGetSymbolAddress((void**)&qn16, g_qn16);
    cudaGetSymbolAddress((void**)&x16,  g_x16);
    cudaGetSymbolAddress((void**)&xlo,  g_xlo);
    cudaGetSymbolAddress((void**)&w16,  g_w16);
    cudaGetSymbolAddress((void**)&whi,  g_whi);
    cudaGetSymbolAddress((void**)&wlo,  g_wlo);
    cudaGetSymbolAddress((void**)&v16,  g_v16);
    cudaGetSymbolAddress((void**)&s16,  g_s16);

    cudaFuncSetAttribute((const void*)q_mma_kernel, cudaFuncAttributeMaxDynamicSharedMemorySize, Q_SMEM);
    cudaFuncSetAttribute((const void*)s_mma_kernel, cudaFuncAttributeMaxDynamicSharedMemorySize, S1_SMEM);
    cudaFuncSetAttribute((const void*)h_mma_kernel, cudaFuncAttributeMaxDynamicSharedMemorySize, H_SMEM);

    // 1) splits: x -> hi/lo fp16, W_qk -> hi/lo fp16, W_v -> fp16
    split_x_kernel<<<((long)ROWS * DIM / 4 + 255) / 256, 256>>>(x, x16, xlo, (long)ROWS * DIM);
    split_w_kernel<<<((long)DIM * DIM / 4 + 255) / 256, 256>>>(W_qk, W_v, whi, wlo, w16);

    // 2) q = x * Wqk^T — 3-pass fp16 split (fp32-equivalent)
    {
        dim3 grid(DIM / 128, ROWS / 128, 1);
        q_mma_kernel<<<grid, 512, Q_SMEM>>>(x16, xlo, whi, wlo, qp);
    }

    // 3) v = x * W_v^T (fp16 1-pass; row-major)
    {
        dim3 grid(DIM / 128, ROWS / 128, 1);
        h_mma_kernel<<<grid, 512, H_SMEM>>>(x16, DIM, w16, DIM, DIM, v16, DIM);
    }

    // 4) L2-normalize q rows + fp16 plane
    l2norm_kernel<<<ROWS, 128>>>(qp, qn16);

    // 5) S = Qn*Qn^T — 1-pass fp16, triangular + mirror, cooperative rescue
    {
        int nt = SEQ / 128;
        dim3 grid(nt * (nt + 1) / 2, 1, BATCH);
        s_mma_kernel<<<grid, 512, S1_SMEM>>>(qn16, qp, s16);
    }

    // 6) out = LayerNorm(S * V) — sparse gather, fused LN
    av_ln_kernel<<<ROWS, 128>>>(s16, v16, gamma, beta, out);
}